// round 14
// baseline (speedup 1.0000x reference)
#include <cuda_runtime.h>
#include <cuda_fp16.h>
#include <math.h>
#include <stdint.h>

// Problem dims
constexpr int BB = 64;
constexpr int TT = 32;
constexpr int SS = 31;     // scan steps (T-1)
constexpr int VV = 10000;
constexpr int EE = 300;
constexpr int HH = 256;
constexpr int FF = 4096;
constexpr int GG = 1024;   // 4*H
constexpr int KIN = HH + EE;   // 556
constexpr int KE = 320;        // EE padded to 32-multiple (emb-part K)
constexpr int MROWS = SS * BB; // 1984

// -------------------- device scratch (static, no allocs) --------------------
__device__ float  d_xpart[16 * BB * HH];
__device__ __half d_xph[BB * HH];          // Xp fp16 (G1 A-matrix)
__device__ __half d_E[MROWS * KE];         // gathered embeddings fp16, K-padded
__device__ float  d_bias2[GG];             // b_ih + b_hh
__device__ float  d_g1[BB * GG];           // Xp @ wih1^T + bias2 (per-batch row)
__device__ float  d_gpre[MROWS * GG];      // full gate inputs
__device__ __half d_Hall[MROWS * HH];      // h history fp16 (fc2 A matrix)
__device__ __half d_logits[MROWS * VV];    // fc2 output, fp16 (40 MB)
__device__ int    d_labels[TT * BB];
__device__ __half d_w2h[VV * HH];          // fc2_w fp16
__device__ __half d_wih1h[GG * HH];        // w_ih cols [0,256) fp16
__device__ __half d_wih2h[GG * KE];        // w_ih cols [256,556) fp16, padded

// -------------------- helpers ------------------------------------------------
__device__ __forceinline__ uint32_t smem_u32(const void* p) {
    return (uint32_t)__cvta_generic_to_shared(p);
}
__device__ __forceinline__ void cp16(void* smem_dst, const void* gsrc, bool pred) {
    uint32_t saddr = smem_u32(smem_dst);
    int sz = pred ? 16 : 0;
    asm volatile("cp.async.cg.shared.global [%0], [%1], 16, %2;\n"
                 :: "r"(saddr), "l"(gsrc), "r"(sz) : "memory");
}
__device__ __forceinline__ void mma_f16(float* d, const uint32_t* a, const uint32_t* b) {
    asm volatile(
        "mma.sync.aligned.m16n8k16.row.col.f32.f16.f16.f32 "
        "{%0,%1,%2,%3}, {%4,%5,%6,%7}, {%8,%9}, {%0,%1,%2,%3};"
        : "+f"(d[0]), "+f"(d[1]), "+f"(d[2]), "+f"(d[3])
        : "r"(a[0]), "r"(a[1]), "r"(a[2]), "r"(a[3]), "r"(b[0]), "r"(b[1]));
}
__device__ __forceinline__ void ldsm_x4(uint32_t& r0, uint32_t& r1,
                                        uint32_t& r2, uint32_t& r3, uint32_t addr) {
    asm volatile("ldmatrix.sync.aligned.m8n8.x4.shared.b16 {%0,%1,%2,%3}, [%4];"
                 : "=r"(r0), "=r"(r1), "=r"(r2), "=r"(r3) : "r"(addr));
}
__device__ __forceinline__ uint2 pack_h4(float4 v) {
    __half2 p0 = __floats2half2_rn(v.x, v.y);
    __half2 p1 = __floats2half2_rn(v.z, v.w);
    uint2 u;
    u.x = *(uint32_t*)&p0;
    u.y = *(uint32_t*)&p1;
    return u;
}
__device__ __forceinline__ float fast_tanh(float x) {
    float r;
    asm("tanh.approx.f32 %0, %1;" : "=f"(r) : "f"(x));
    return r;
}
__device__ __forceinline__ float fast_sigmoid(float x) {
    return 1.f / (1.f + __expf(-x));
}
#define CP_COMMIT() asm volatile("cp.async.commit_group;\n" ::: "memory")

// -------------------- fc1: Xp = X @ fc1_w.T + b (split-K SIMT) ---------------
__global__ void __launch_bounds__(256) k_fc1(const float* __restrict__ X,
                                             const float* __restrict__ W) {
    const int h0 = blockIdx.x * 32;
    const int kb = blockIdx.y;
    const int kbase = kb * 256;
    const int tid = threadIdx.x;
    __shared__ __align__(16) float Xs[32][68];
    __shared__ float Wsh[32][33];
    float acc[4][2];
#pragma unroll
    for (int q = 0; q < 4; q++) { acc[q][0] = 0.f; acc[q][1] = 0.f; }
    const int tb = (tid & 15) * 4;
    const int th = (tid >> 4) * 2;

    for (int t = 0; t < 8; t++) {
        int k0 = kbase + t * 32;
#pragma unroll
        for (int i = 0; i < 8; i++) {
            int idx = tid + i * 256;
            int b = idx >> 5, kk = idx & 31;
            Xs[kk][b] = X[(size_t)b * FF + k0 + kk];
        }
#pragma unroll
        for (int i = 0; i < 4; i++) {
            int idx = tid + i * 256;
            int hh = idx >> 5, kk = idx & 31;
            Wsh[kk][hh] = W[(size_t)(h0 + hh) * FF + k0 + kk];
        }
        __syncthreads();
#pragma unroll
        for (int kk = 0; kk < 32; kk++) {
            float4 x4 = *(const float4*)&Xs[kk][tb];
            float w0 = Wsh[kk][th], w1 = Wsh[kk][th + 1];
            acc[0][0] += x4.x * w0; acc[0][1] += x4.x * w1;
            acc[1][0] += x4.y * w0; acc[1][1] += x4.y * w1;
            acc[2][0] += x4.z * w0; acc[2][1] += x4.z * w1;
            acc[3][0] += x4.w * w0; acc[3][1] += x4.w * w1;
        }
        __syncthreads();
    }
#pragma unroll
    for (int q = 0; q < 4; q++)
#pragma unroll
        for (int j = 0; j < 2; j++)
            d_xpart[kb * (BB * HH) + (tb + q) * HH + h0 + th + j] = acc[q][j];
}

// -------------------- fc1 reduce (fp16 out) + labels + bias2 -----------------
__global__ void k_fc1red(const float* __restrict__ fc1_b,
                         const int* __restrict__ lab,
                         const float* __restrict__ bih,
                         const float* __restrict__ bhh) {
    const int blk = blockIdx.x;
    const int tid = threadIdx.x;
    if (blk < 16) {
        int i4 = blk * 256 + tid;
        const float4* bp = (const float4*)fc1_b;
        float4 s = bp[i4 & 63];
#pragma unroll
        for (int kb = 0; kb < 16; kb++) {
            float4 p = ((const float4*)(d_xpart + kb * BB * HH))[i4];
            s.x += p.x; s.y += p.y; s.z += p.z; s.w += p.w;
        }
        ((uint2*)d_xph)[i4] = pack_h4(s);
    } else if (blk == 16) {
        __shared__ int is64;
        if (tid == 0) {
            int f = 1;
            for (int i = 1; i < 64 && f; i += 2)
                if (lab[i] != 0) f = 0;
            is64 = f;
        }
        __syncthreads();
        for (int i = tid; i < TT * BB; i += 256)
            d_labels[i] = is64 ? (int)(((const long long*)lab)[i]) : lab[i];
    } else {
        for (int i = tid; i < GG; i += 256)
            d_bias2[i] = bih[i] + bhh[i];
    }
}

// -------------------- merged elementwise: E + wih1 + wih2 + fc2w -------------
constexpr int E4 = KE / 4;                  // 80 groups per E row
constexpr int RE  = MROWS * E4;             // 158720
constexpr int RW1 = GG * (HH / 4);          // 65536
constexpr int RW2 = GG * E4;                // 81920
constexpr int R3  = VV * HH / 4;            // 640000
constexpr int RALL = RE + RW1 + RW2 + R3;   // 946176 (divisible by 256)
__global__ void __launch_bounds__(256) k_cvtall(const float* __restrict__ emb_table,
                                                const float* __restrict__ wih,
                                                const float* __restrict__ fc2w) {
    int idx = blockIdx.x * 256 + threadIdx.x;
    if (idx < RE) {                         // E = gathered embeddings, padded
        int r = idx / E4, c = idx - r * E4;
        int s = r >> 6, b = r & 63;
        float4 v = make_float4(0.f, 0.f, 0.f, 0.f);
        if (c < 75) {                       // 75*4 = 300 = EE exactly
            int tok = (s == 0) ? 1 : d_labels[s * BB + b];   // START_ID = 1
            v = *(const float4*)(emb_table + (size_t)tok * EE + c * 4);
        }
        ((uint2*)d_E)[idx] = pack_h4(v);
    } else if (idx < RE + RW1) {            // wih cols [0,256)
        int i = idx - RE;
        int r = i >> 6, c = i & 63;
        float4 v = *(const float4*)(wih + (size_t)r * KIN + c * 4);
        ((uint2*)d_wih1h)[i] = pack_h4(v);
    } else if (idx < RE + RW1 + RW2) {      // wih cols [256,556), padded
        int i = idx - (RE + RW1);
        int r = i / E4, c = i - r * E4;
        float4 v = (c < 75) ? *(const float4*)(wih + (size_t)r * KIN + HH + c * 4)
                            : make_float4(0.f, 0.f, 0.f, 0.f);
        ((uint2*)d_wih2h)[i] = pack_h4(v);
    } else if (idx < RALL) {                // fc2_w -> fp16
        int i = idx - (RE + RW1 + RW2);
        ((uint2*)d_w2h)[i] = pack_h4(((const float4*)fc2w)[i]);
    }
}

// -------------------- fp16 TC GEMM, 128x128 tile, 3-stage pipeline (fc2) -----
constexpr int ST2 = 3;
constexpr int H_ASTG = 128 * 40;
constexpr int H_BSTG = 128 * 40;
constexpr int SMEM_HG = ST2 * (H_ASTG + H_BSTG) * 2;   // 61440 B
__global__ void __launch_bounds__(256) k_hgemm(
    const __half* __restrict__ A, int lda,
    const __half* __restrict__ B, int ldb,
    const float* __restrict__ bias,
    __half* __restrict__ C, int ldc,
    int M, int N, int K)
{
    extern __shared__ __half sm[];
    __half* AsB = sm;
    __half* BsB = sm + ST2 * H_ASTG;

    const int tid = threadIdx.x;
    const int lane = tid & 31;
    const int warpId = tid >> 5;
    const int warpM = warpId & 3;
    const int warpN = warpId >> 2;
    const int g = lane >> 2;
    const int t = lane & 3;
    const int lr16 = lane & 15;
    const int lk8 = (lane >> 4) * 8;

    const int ncol = blockIdx.x * 128;
    const int mrow = blockIdx.y * 128;

    float acc[2][8][4];
#pragma unroll
    for (int mt = 0; mt < 2; mt++)
#pragma unroll
        for (int nt = 0; nt < 8; nt++)
#pragma unroll
            for (int q = 0; q < 4; q++) acc[mt][nt][q] = 0.f;

    const int NT = K >> 5;

    auto load_tile = [&](int st, int kt) {
        int k0 = kt << 5;
        __half* As = AsB + st * H_ASTG;
        __half* Bs = BsB + st * H_BSTG;
#pragma unroll
        for (int i = 0; i < 2; i++) {
            int c = tid + i * 256;
            int m = c >> 2, kc = (c & 3) * 8;
            cp16(As + m * 40 + kc, A + (size_t)(mrow + m) * lda + k0 + kc,
                 (mrow + m) < M);
        }
#pragma unroll
        for (int i = 0; i < 2; i++) {
            int c = tid + i * 256;
            int n = c >> 2, kc = (c & 3) * 8;
            cp16(Bs + n * 40 + kc, B + (size_t)(ncol + n) * ldb + k0 + kc,
                 (ncol + n) < N);
        }
    };

#pragma unroll
    for (int p = 0; p < ST2 - 1; p++) {
        if (p < NT) load_tile(p, p);
        CP_COMMIT();
    }

    for (int kt = 0; kt < NT; kt++) {
        int st = kt % ST2;
        if (kt + ST2 - 1 < NT) load_tile((kt + ST2 - 1) % ST2, kt + ST2 - 1);
        CP_COMMIT();
        asm volatile("cp.async.wait_group %0;\n" :: "n"(ST2 - 1) : "memory");
        __syncthreads();

        const __half* As = AsB + st * H_ASTG;
        const __half* Bs = BsB + st * H_BSTG;
#pragma unroll
        for (int ks = 0; ks < 32; ks += 16) {
            uint32_t afr[2][4], bfr[8][2];
#pragma unroll
            for (int mt = 0; mt < 2; mt++) {
                ldsm_x4(afr[mt][0], afr[mt][1], afr[mt][2], afr[mt][3],
                        smem_u32(As + (warpM * 32 + mt * 16 + lr16) * 40 + ks + lk8));
            }
#pragma unroll
            for (int ntp = 0; ntp < 4; ntp++) {
                uint32_t q0, q1, q2, q3;
                ldsm_x4(q0, q1, q2, q3,
                        smem_u32(Bs + (warpN * 64 + ntp * 16 + lr16) * 40 + ks + lk8));
                bfr[2 * ntp][0]     = q0;
                bfr[2 * ntp + 1][0] = q1;
                bfr[2 * ntp][1]     = q2;
                bfr[2 * ntp + 1][1] = q3;
            }
#pragma unroll
            for (int mt = 0; mt < 2; mt++)
#pragma unroll
                for (int nt = 0; nt < 8; nt++)
                    mma_f16(acc[mt][nt], afr[mt], bfr[nt]);
        }
        __syncthreads();
    }

#pragma unroll
    for (int mt = 0; mt < 2; mt++) {
#pragma unroll
        for (int nt = 0; nt < 8; nt++) {
            int m0 = mrow + warpM * 32 + mt * 16 + g;
            int n0 = ncol + warpN * 64 + nt * 8 + 2 * t;
            if (n0 < N) {
                float b0 = bias[n0], b1 = bias[n0 + 1];
                if (m0 < M) {
                    __half2 h01 = __floats2half2_rn(acc[mt][nt][0] + b0,
                                                    acc[mt][nt][1] + b1);
                    *(uint32_t*)&C[(size_t)m0 * ldc + n0] = *(uint32_t*)&h01;
                }
                if (m0 + 8 < M) {
                    __half2 h23 = __floats2half2_rn(acc[mt][nt][2] + b0,
                                                    acc[mt][nt][3] + b1);
                    *(uint32_t*)&C[(size_t)(m0 + 8) * ldc + n0] = *(uint32_t*)&h23;
                }
            }
        }
    }
}

// -------------------- fp16 TC GEMM, 64x128 tile, 4-stage (G1 / G2) -----------
// PERROW=0: bias[n]. PERROW=1: bias[(row & 63) * GG + n]  (adds G1 row).
constexpr int ST4 = 4;
constexpr int H64_ASTG = 64 * 40;
constexpr int H64_BSTG = 128 * 40;
constexpr int SMEM_HG64 = ST4 * (H64_ASTG + H64_BSTG) * 2;   // 61440 B
template <int PERROW>
__global__ void __launch_bounds__(256) k_hgemm64(
    const __half* __restrict__ A, int lda,
    const __half* __restrict__ B, int ldb,
    const float* __restrict__ bias,
    float* __restrict__ C, int ldc,
    int M, int N, int K)
{
    extern __shared__ __half sm[];
    __half* AsB = sm;
    __half* BsB = sm + ST4 * H64_ASTG;

    const int tid = threadIdx.x;
    const int lane = tid & 31;
    const int warpId = tid >> 5;
    const int warpM = warpId & 1;
    const int warpN = warpId >> 1;
    const int g = lane >> 2;
    const int t = lane & 3;
    const int lr16 = lane & 15;
    const int lk8 = (lane >> 4) * 8;

    const int ncol = blockIdx.x * 128;
    const int mrow = blockIdx.y * 64;

    float acc[2][4][4];
#pragma unroll
    for (int mt = 0; mt < 2; mt++)
#pragma unroll
        for (int nt = 0; nt < 4; nt++)
#pragma unroll
            for (int q = 0; q < 4; q++) acc[mt][nt][q] = 0.f;

    const int NT = K >> 5;

    auto load_tile = [&](int st, int kt) {
        int k0 = kt << 5;
        __half* As = AsB + st * H64_ASTG;
        __half* Bs = BsB + st * H64_BSTG;
        {
            int c = tid;
            int m = c >> 2, kc = (c & 3) * 8;
            cp16(As + m * 40 + kc, A + (size_t)(mrow + m) * lda + k0 + kc,
                 (mrow + m) < M);
        }
#pragma unroll
        for (int i = 0; i < 2; i++) {
            int c = tid + i * 256;
            int n = c >> 2, kc = (c & 3) * 8;
            cp16(Bs + n * 40 + kc, B + (size_t)(ncol + n) * ldb + k0 + kc,
                 (ncol + n) < N);
        }
    };

#pragma unroll
    for (int p = 0; p < ST4 - 1; p++) {
        if (p < NT) load_tile(p, p);
        CP_COMMIT();
    }

    for (int kt = 0; kt < NT; kt++) {
        int st = kt % ST4;
        if (kt + ST4 - 1 < NT) load_tile((kt + ST4 - 1) % ST4, kt + ST4 - 1);
        CP_COMMIT();
        asm volatile("cp.async.wait_group %0;\n" :: "n"(ST4 - 1) : "memory");
        __syncthreads();

        const __half* As = AsB + st * H64_ASTG;
        const __half* Bs = BsB + st * H64_BSTG;
#pragma unroll
        for (int ks = 0; ks < 32; ks += 16) {
            uint32_t afr[2][4], bfr[4][2];
#pragma unroll
            for (int mt = 0; mt < 2; mt++) {
                ldsm_x4(afr[mt][0], afr[mt][1], afr[mt][2], afr[mt][3],
                        smem_u32(As + (warpM * 32 + mt * 16 + lr16) * 40 + ks + lk8));
            }
#pragma unroll
            for (int ntp = 0; ntp < 2; ntp++) {
                uint32_t q0, q1, q2, q3;
                ldsm_x4(q0, q1, q2, q3,
                        smem_u32(Bs + (warpN * 32 + ntp * 16 + lr16) * 40 + ks + lk8));
                bfr[2 * ntp][0]     = q0;
                bfr[2 * ntp + 1][0] = q1;
                bfr[2 * ntp][1]     = q2;
                bfr[2 * ntp + 1][1] = q3;
            }
#pragma unroll
            for (int mt = 0; mt < 2; mt++)
#pragma unroll
                for (int nt = 0; nt < 4; nt++)
                    mma_f16(acc[mt][nt], afr[mt], bfr[nt]);
        }
        __syncthreads();
    }

#pragma unroll
    for (int mt = 0; mt < 2; mt++) {
#pragma unroll
        for (int nt = 0; nt < 4; nt++) {
            int m0 = mrow + warpM * 32 + mt * 16 + g;
            int n0 = ncol + warpN * 32 + nt * 8 + 2 * t;
            if (n0 < N) {
                if (PERROW) {
                    if (m0 < M) {
                        const float* br = bias + (size_t)(m0 & 63) * GG + n0;
                        C[(size_t)m0 * ldc + n0]     = acc[mt][nt][0] + br[0];
                        C[(size_t)m0 * ldc + n0 + 1] = acc[mt][nt][1] + br[1];
                    }
                    if (m0 + 8 < M) {
                        const float* br = bias + (size_t)((m0 + 8) & 63) * GG + n0;
                        C[(size_t)(m0 + 8) * ldc + n0]     = acc[mt][nt][2] + br[0];
                        C[(size_t)(m0 + 8) * ldc + n0 + 1] = acc[mt][nt][3] + br[1];
                    }
                } else {
                    float b0 = bias[n0], b1 = bias[n0 + 1];
                    if (m0 < M) {
                        C[(size_t)m0 * ldc + n0]     = acc[mt][nt][0] + b0;
                        C[(size_t)m0 * ldc + n0 + 1] = acc[mt][nt][1] + b1;
                    }
                    if (m0 + 8 < M) {
                        C[(size_t)(m0 + 8) * ldc + n0]     = acc[mt][nt][2] + b0;
                        C[(size_t)(m0 + 8) * ldc + n0 + 1] = acc[mt][nt][3] + b1;
                    }
                }
            }
        }
    }
}

// -------------------- recurrence: 4 clusters x 8 CTAs ------------------------
__global__ void __launch_bounds__(256, 1) __cluster_dims__(8, 1, 1)
k_rec(const float* __restrict__ w_hh) {
    __shared__ __align__(16) __half hs[16][264];
    __shared__ float gbuf[16][132];

    const int tid = threadIdx.x;
    const int lane = tid & 31;
    const int wid = tid >> 5;
    const int g = lane >> 2;
    const int t = lane & 3;
    const int lr16 = lane & 15;
    const int lk8 = (lane >> 4) * 8;
    const int rank = blockIdx.x & 7;
    const int grp = blockIdx.x >> 3;
    const int j0 = rank * 32;
    const int brow0 = grp * 16;

    uint32_t wb[2][16][2];
#pragma unroll
    for (int nt = 0; nt < 2; nt++) {
        int lc = wid * 16 + nt * 8 + g;
        int wrow = (lc >> 5) * 256 + j0 + (lc & 31);
        const float* wr = w_hh + (size_t)wrow * HH;
#pragma unroll
        for (int kt = 0; kt < 16; kt++) {
            __half2 h0 = __floats2half2_rn(wr[kt * 16 + 2 * t], wr[kt * 16 + 2 * t + 1]);
            __half2 h1 = __floats2half2_rn(wr[kt * 16 + 2 * t + 8], wr[kt * 16 + 2 * t + 9]);
            wb[nt][kt][0] = *(uint32_t*)&h0;
            wb[nt][kt][1] = *(uint32_t*)&h1;
        }
    }

    float creg[2] = {0.f, 0.f};
    const int crow = tid >> 4;
    const int cj2 = (tid & 15) * 2;
    int lc0[2], r0[2];
#pragma unroll
    for (int nt = 0; nt < 2; nt++) {
        lc0[nt] = wid * 16 + nt * 8 + 2 * t;
        r0[nt] = (lc0[nt] >> 5) * 256 + j0 + (lc0[nt] & 31);
    }

    for (int s = 0; s < SS; s++) {
        const float* gp = d_gpre + ((size_t)s * BB + brow0) * GG;
        float2 q0[2], q1[2];
#pragma unroll
        for (int nt = 0; nt < 2; nt++) {
            q0[nt] = *(const float2*)&gp[(size_t)g * GG + r0[nt]];
            q1[nt] = *(const float2*)&gp[(size_t)(g + 8) * GG + r0[nt]];
        }

        float accA[2][4] = {{0.f, 0.f, 0.f, 0.f}, {0.f, 0.f, 0.f, 0.f}};
        float accB[2][4] = {{0.f, 0.f, 0.f, 0.f}, {0.f, 0.f, 0.f, 0.f}};

        if (s > 0) {
            const uint4* src = (const uint4*)(d_Hall + ((size_t)(s - 1) * BB + brow0) * HH);
#pragma unroll
            for (int i = 0; i < 2; i++) {
                int c = tid + i * 256;
                int m = c >> 5, kc = c & 31;
                *(uint4*)&hs[m][kc * 8] = src[m * 32 + kc];
            }
            __syncthreads();
#pragma unroll
            for (int kt = 0; kt < 16; kt++) {
                uint32_t af[4];
                ldsm_x4(af[0], af[1], af[2], af[3],
                        smem_u32(&hs[lr16][kt * 16 + lk8]));
                float* d0 = (kt < 8) ? accA[0] : accB[0];
                float* d1 = (kt < 8) ? accA[1] : accB[1];
                mma_f16(d0, af, wb[0][kt]);
                mma_f16(d1, af, wb[1][kt]);
            }
        }

#pragma unroll
        for (int nt = 0; nt < 2; nt++) {
            gbuf[g][lc0[nt]]         = accA[nt][0] + accB[nt][0] + q0[nt].x;
            gbuf[g][lc0[nt] + 1]     = accA[nt][1] + accB[nt][1] + q0[nt].y;
            gbuf[g + 8][lc0[nt]]     = accA[nt][2] + accB[nt][2] + q1[nt].x;
            gbuf[g + 8][lc0[nt] + 1] = accA[nt][3] + accB[nt][3] + q1[nt].y;
        }
        __syncthreads();

        {
            float hv[2];
#pragma unroll
            for (int e = 0; e < 2; e++) {
                int jj = cj2 + e;
                float gi = gbuf[crow][jj],      gf = gbuf[crow][32 + jj];
                float gc = gbuf[crow][64 + jj], go = gbuf[crow][96 + jj];
                float ii = fast_sigmoid(gi);
                float ff = fast_sigmoid(gf);
                float gv = fast_tanh(gc);
                float oo = fast_sigmoid(go);
                float cn = ff * creg[e] + ii * gv;
                creg[e] = cn;
                hv[e] = oo * fast_tanh(cn);
            }
            __half2 hp = __floats2half2_rn(hv[0], hv[1]);
            *(uint32_t*)&d_Hall[((size_t)s * BB + brow0 + crow) * HH + j0 + cj2] =
                *(uint32_t*)&hp;
        }

        if (s + 1 < SS) {
            asm volatile("barrier.cluster.arrive.aligned;" ::: "memory");
            asm volatile("barrier.cluster.wait.aligned;" ::: "memory");
        }
    }
}

// -------------------- fused one-hot + log-softmax (register-cached row) ------
constexpr int V8 = VV / 8;   // 1250 uint4 groups
__global__ void __launch_bounds__(256) k_softmax(float* __restrict__ out) {
    const int r = blockIdx.x;
    const int tid = threadIdx.x;
    if (r >= MROWS) {
        int b = r - MROWS;
        float* dst = out + (size_t)b * TT * VV;
        for (int v = tid * 4; v < VV; v += 1024) {
            float4 z = make_float4(0.f, 0.f, 0.f, 0.f);
            if (v == 0) z.y = 1.f;         // index 1 = START_ID
            __stcs((float4*)(dst + v), z);
        }
        return;
    }
    const int s = r >> 6, b = r & 63;
    const uint4* src = (const uint4*)(d_logits + (size_t)r * VV);

    uint4 vals[5];
    float m = -1e30f, sum = 0.f;
#pragma unroll
    for (int i = 0; i < 5; i++) {
        int c = tid + i * 256;
        if (c < V8) {
            uint4 u = src[c];
            vals[i] = u;
            float2 f0 = __half22float2(*(__half2*)&u.x);
            float2 f1 = __half22float2(*(__half2*)&u.y);
            float2 f2 = __half22float2(*(__half2*)&u.z);
            float2 f3 = __half22float2(*(__half2*)&u.w);
            float m8 = fmaxf(fmaxf(fmaxf(f0.x, f0.y), fmaxf(f1.x, f1.y)),
                             fmaxf(fmaxf(f2.x, f2.y), fmaxf(f3.x, f3.y)));
            if (m8 > m) { sum *= __expf(m - m8); m = m8; }
            sum += __expf(f0.x - m) + __expf(f0.y - m)
                 + __expf(f1.x - m) + __expf(f1.y - m)
                 + __expf(f2.x - m) + __expf(f2.y - m)
                 + __expf(f3.x - m) + __expf(f3.y - m);
        }
    }
#pragma unroll
    for (int o = 16; o; o >>= 1) {
        float mo = __shfl_xor_sync(0xffffffffu, m, o);
        float so = __shfl_xor_sync(0xffffffffu, sum, o);
        float M = fmaxf(m, mo);
        sum = sum * __expf(m - M) + so * __expf(mo - M);
        m = M;
    }
    __shared__ float sm_m[8], sm_s[8], s_lz;
    if ((tid & 31) == 0) { sm_m[tid >> 5] = m; sm_s[tid >> 5] = sum; }
    __syncthreads();
    if (tid == 0) {
        float M = sm_m[0], S = sm_s[0];
#pragma unroll
        for (int w = 1; w < 8; w++) {
            float mo = sm_m[w], so = sm_s[w];
            float MM = fmaxf(M, mo);
            S = S * __expf(M - MM) + so * __expf(mo - MM);
            M = MM;
        }
        s_lz = M + logf(S);
    }
    __syncthreads();
    const float lz = s_lz;
    float4* dst = (float4*)(out + ((size_t)b * TT + s + 1) * VV);
#pragma unroll
    for (int i = 0; i < 5; i++) {
        int c = tid + i * 256;
        if (c < V8) {
            uint4 u = vals[i];
            float2 f0 = __half22float2(*(__half2*)&u.x);
            float2 f1 = __half22float2(*(__half2*)&u.y);
            float2 f2 = __half22float2(*(__half2*)&u.z);
            float2 f3 = __half22float2(*(__half2*)&u.w);
            __stcs(&dst[2 * c],
                   make_float4(f0.x - lz, f0.y - lz, f1.x - lz, f1.y - lz));
            __stcs(&dst[2 * c + 1],
                   make_float4(f2.x - lz, f2.y - lz, f3.x - lz, f3.y - lz));
        }
    }
}

// -------------------- launch ------------------------------------------------
extern "C" void kernel_launch(void* const* d_in, const int* in_sizes, int n_in,
                              void* d_out, int out_size) {
    const float* X    = (const float*)d_in[0];
    const float* emb  = (const float*)d_in[1];
    const float* fc1w = (const float*)d_in[2];
    const float* fc1b = (const float*)d_in[3];
    const float* wih  = (const float*)d_in[4];
    const float* whh  = (const float*)d_in[5];
    const float* bih  = (const float*)d_in[6];
    const float* bhh  = (const float*)d_in[7];
    const float* fc2w = (const float*)d_in[8];
    const float* fc2b = (const float*)d_in[9];
    const int*   lab  = (const int*)d_in[10];
    float* out = (float*)d_out;

    __half *pXph, *pE, *pHall, *pW2h, *pWih1, *pWih2, *pLogits;
    float *pBias2, *pG1, *pGpre;
    cudaGetSymbolAddress((void**)&pXph,    d_xph);
    cudaGetSymbolAddress((void**)&pE,      d_E);
    cudaGetSymbolAddress((void**)&pBias2,  d_bias2);
    cudaGetSymbolAddress((void**)&pG1,     d_g1);
    cudaGetSymbolAddress((void**)&pGpre,   d_gpre);
    cudaGetSymbolAddress((void**)&pHall,   d_Hall);
    cudaGetSymbolAddress((void**)&pLogits, d_logits);
    cudaGetSymbolAddress((void**)&pW2h,    d_w2h);
    cudaGetSymbolAddress((void**)&pWih1,   d_wih1h);
    cudaGetSymbolAddress((void**)&pWih2,   d_wih2h);

    static int attr_set = 0;
    if (!attr_set) {
        cudaFuncSetAttribute(k_hgemm,
                             cudaFuncAttributeMaxDynamicSharedMemorySize, SMEM_HG);
        cudaFuncSetAttribute(k_hgemm64<0>,
                             cudaFuncAttributeMaxDynamicSharedMemorySize, SMEM_HG64);
        cudaFuncSetAttribute(k_hgemm64<1>,
                             cudaFuncAttributeMaxDynamicSharedMemorySize, SMEM_HG64);
        attr_set = 1;
    }

    k_fc1<<<dim3(8, 16), 256>>>(X, fc1w);
    k_fc1red<<<18, 256>>>(fc1b, lab, bih, bhh);
    k_cvtall<<<RALL / 256, 256>>>(emb, wih, fc2w);

    // G1[64,1024] = Xp @ wih1^T + bias2   (K=256, 8 CTAs)
    k_hgemm64<0><<<dim3(8, 1), 256, SMEM_HG64>>>(pXph, HH, pWih1, HH, pBias2,
                                                 pG1, GG, BB, GG, HH);

    // gpre[1984,1024] = E @ wih2^T + G1[row&63]   (K=320, 248 CTAs)
    k_hgemm64<1><<<dim3(8, 31), 256, SMEM_HG64>>>(pE, KE, pWih2, KE, pG1,
                                                  pGpre, GG, MROWS, GG, KE);

    // recurrence: 32 CTAs = 4 clusters x 8 (cluster barrier between steps)
    k_rec<<<32, 256>>>(whh);

    // fc2: logits[1984,10000] (fp16) = Hall @ w2h^T + fc2b, 3-stage pipeline
    k_hgemm<<<dim3(79, 16), 256, SMEM_HG>>>(pHall, HH, pW2h, HH, fc2b,
                                            pLogits, VV, MROWS, VV, HH);

    k_softmax<<<MROWS + BB, 256>>>(out);
}

// round 15
// speedup vs baseline: 1.0337x; 1.0337x over previous
#include <cuda_runtime.h>
#include <cuda_fp16.h>
#include <math.h>
#include <stdint.h>

// Problem dims
constexpr int BB = 64;
constexpr int TT = 32;
constexpr int SS = 31;     // scan steps (T-1)
constexpr int VV = 10000;
constexpr int EE = 300;
constexpr int HH = 256;
constexpr int FF = 4096;
constexpr int GG = 1024;   // 4*H
constexpr int KIN = HH + EE;   // 556
constexpr int KE = 320;        // EE padded to 32-multiple
constexpr int MROWS = SS * BB; // 1984

// -------------------- device scratch (static, no allocs) --------------------
__device__ float  d_xpart[16 * BB * HH];
__device__ __half d_xph[BB * HH];          // Xp fp16 (G1 A-matrix)
__device__ __half d_E[MROWS * KE];         // gathered embeddings fp16, padded
__device__ float  d_bias2[GG];             // b_ih + b_hh
__device__ float  d_g1[BB * GG];           // Xp @ wih1^T + bias2
__device__ float  d_g2[MROWS * GG];        // E @ wih2^T (no bias)
__device__ __half d_Hall[MROWS * HH];      // h history fp16 (fc2 A matrix)
__device__ __half d_logits[MROWS * VV];    // fc2 output, fp16 (40 MB)
__device__ int    d_labels[TT * BB];
__device__ __half d_w2h[VV * HH];          // fc2_w fp16
__device__ __half d_wih1h[GG * HH];        // w_ih cols [0,256) fp16
__device__ __half d_wih2h[GG * KE];        // w_ih cols [256,556) fp16, padded

// -------------------- helpers ------------------------------------------------
__device__ __forceinline__ uint32_t smem_u32(const void* p) {
    return (uint32_t)__cvta_generic_to_shared(p);
}
__device__ __forceinline__ void cp16(void* smem_dst, const void* gsrc, bool pred) {
    uint32_t saddr = smem_u32(smem_dst);
    int sz = pred ? 16 : 0;
    asm volatile("cp.async.cg.shared.global [%0], [%1], 16, %2;\n"
                 :: "r"(saddr), "l"(gsrc), "r"(sz) : "memory");
}
__device__ __forceinline__ void mma_f16(float* d, const uint32_t* a, const uint32_t* b) {
    asm volatile(
        "mma.sync.aligned.m16n8k16.row.col.f32.f16.f16.f32 "
        "{%0,%1,%2,%3}, {%4,%5,%6,%7}, {%8,%9}, {%0,%1,%2,%3};"
        : "+f"(d[0]), "+f"(d[1]), "+f"(d[2]), "+f"(d[3])
        : "r"(a[0]), "r"(a[1]), "r"(a[2]), "r"(a[3]), "r"(b[0]), "r"(b[1]));
}
__device__ __forceinline__ void ldsm_x4(uint32_t& r0, uint32_t& r1,
                                        uint32_t& r2, uint32_t& r3, uint32_t addr) {
    asm volatile("ldmatrix.sync.aligned.m8n8.x4.shared.b16 {%0,%1,%2,%3}, [%4];"
                 : "=r"(r0), "=r"(r1), "=r"(r2), "=r"(r3) : "r"(addr));
}
__device__ __forceinline__ uint2 pack_h4(float4 v) {
    __half2 p0 = __floats2half2_rn(v.x, v.y);
    __half2 p1 = __floats2half2_rn(v.z, v.w);
    uint2 u;
    u.x = *(uint32_t*)&p0;
    u.y = *(uint32_t*)&p1;
    return u;
}
__device__ __forceinline__ float fast_tanh(float x) {
    float r;
    asm("tanh.approx.f32 %0, %1;" : "=f"(r) : "f"(x));
    return r;
}
__device__ __forceinline__ float fast_sigmoid(float x) {
    return 1.f / (1.f + __expf(-x));
}
#define CP_COMMIT() asm volatile("cp.async.commit_group;\n" ::: "memory")

// -------------------- fc1: Xp = X @ fc1_w.T + b (split-K SIMT) ---------------
__global__ void __launch_bounds__(256) k_fc1(const float* __restrict__ X,
                                             const float* __restrict__ W) {
    const int h0 = blockIdx.x * 32;
    const int kb = blockIdx.y;
    const int kbase = kb * 256;
    const int tid = threadIdx.x;
    __shared__ __align__(16) float Xs[32][68];
    __shared__ float Wsh[32][33];
    float acc[4][2];
#pragma unroll
    for (int q = 0; q < 4; q++) { acc[q][0] = 0.f; acc[q][1] = 0.f; }
    const int tb = (tid & 15) * 4;
    const int th = (tid >> 4) * 2;

    for (int t = 0; t < 8; t++) {
        int k0 = kbase + t * 32;
#pragma unroll
        for (int i = 0; i < 8; i++) {
            int idx = tid + i * 256;
            int b = idx >> 5, kk = idx & 31;
            Xs[kk][b] = X[(size_t)b * FF + k0 + kk];
        }
#pragma unroll
        for (int i = 0; i < 4; i++) {
            int idx = tid + i * 256;
            int hh = idx >> 5, kk = idx & 31;
            Wsh[kk][hh] = W[(size_t)(h0 + hh) * FF + k0 + kk];
        }
        __syncthreads();
#pragma unroll
        for (int kk = 0; kk < 32; kk++) {
            float4 x4 = *(const float4*)&Xs[kk][tb];
            float w0 = Wsh[kk][th], w1 = Wsh[kk][th + 1];
            acc[0][0] += x4.x * w0; acc[0][1] += x4.x * w1;
            acc[1][0] += x4.y * w0; acc[1][1] += x4.y * w1;
            acc[2][0] += x4.z * w0; acc[2][1] += x4.z * w1;
            acc[3][0] += x4.w * w0; acc[3][1] += x4.w * w1;
        }
        __syncthreads();
    }
#pragma unroll
    for (int q = 0; q < 4; q++)
#pragma unroll
        for (int j = 0; j < 2; j++)
            d_xpart[kb * (BB * HH) + (tb + q) * HH + h0 + th + j] = acc[q][j];
}

// -------------------- fc1 reduce (fp16 out) + labels + bias2 -----------------
__global__ void k_fc1red(const float* __restrict__ fc1_b,
                         const int* __restrict__ lab,
                         const float* __restrict__ bih,
                         const float* __restrict__ bhh) {
    const int blk = blockIdx.x;
    const int tid = threadIdx.x;
    if (blk < 16) {
        int i4 = blk * 256 + tid;
        const float4* bp = (const float4*)fc1_b;
        float4 s = bp[i4 & 63];
#pragma unroll
        for (int kb = 0; kb < 16; kb++) {
            float4 p = ((const float4*)(d_xpart + kb * BB * HH))[i4];
            s.x += p.x; s.y += p.y; s.z += p.z; s.w += p.w;
        }
        ((uint2*)d_xph)[i4] = pack_h4(s);
    } else if (blk == 16) {
        __shared__ int is64;
        if (tid == 0) {
            int f = 1;
            for (int i = 1; i < 64 && f; i += 2)
                if (lab[i] != 0) f = 0;
            is64 = f;
        }
        __syncthreads();
        for (int i = tid; i < TT * BB; i += 256)
            d_labels[i] = is64 ? (int)(((const long long*)lab)[i]) : lab[i];
    } else {
        for (int i = tid; i < GG; i += 256)
            d_bias2[i] = bih[i] + bhh[i];
    }
}

// -------------------- merged elementwise: E + wih1 + wih2 + fc2w -------------
constexpr int E4 = KE / 4;                  // 80 groups per E row
constexpr int RE  = MROWS * E4;             // 158720
constexpr int RW1 = GG * (HH / 4);          // 65536
constexpr int RW2 = GG * E4;                // 81920
constexpr int R3  = VV * HH / 4;            // 640000
constexpr int RALL = RE + RW1 + RW2 + R3;   // 946176
__global__ void __launch_bounds__(256) k_cvtall(const float* __restrict__ emb_table,
                                                const float* __restrict__ wih,
                                                const float* __restrict__ fc2w) {
    int idx = blockIdx.x * 256 + threadIdx.x;
    if (idx < RE) {                         // E = gathered embeddings, padded
        int r = idx / E4, c = idx - r * E4;
        int s = r >> 6, b = r & 63;
        float4 v = make_float4(0.f, 0.f, 0.f, 0.f);
        if (c < 75) {                       // 75*4 = 300 = EE exactly
            int tok = (s == 0) ? 1 : d_labels[s * BB + b];   // START_ID = 1
            v = *(const float4*)(emb_table + (size_t)tok * EE + c * 4);
        }
        ((uint2*)d_E)[idx] = pack_h4(v);
    } else if (idx < RE + RW1) {            // wih cols [0,256)
        int i = idx - RE;
        int r = i >> 6, c = i & 63;
        float4 v = *(const float4*)(wih + (size_t)r * KIN + c * 4);
        ((uint2*)d_wih1h)[i] = pack_h4(v);
    } else if (idx < RE + RW1 + RW2) {      // wih cols [256,556), padded
        int i = idx - (RE + RW1);
        int r = i / E4, c = i - r * E4;
        float4 v = (c < 75) ? *(const float4*)(wih + (size_t)r * KIN + HH + c * 4)
                            : make_float4(0.f, 0.f, 0.f, 0.f);
        ((uint2*)d_wih2h)[i] = pack_h4(v);
    } else if (idx < RALL) {                // fc2_w -> fp16
        int i = idx - (RE + RW1 + RW2);
        ((uint2*)d_w2h)[i] = pack_h4(((const float4*)fc2w)[i]);
    }
}

// -------------------- fp16 TC GEMM, 128x128 tile, 3-stage pipeline (fc2) -----
constexpr int ST2 = 3;
constexpr int H_ASTG = 128 * 40;
constexpr int H_BSTG = 128 * 40;
constexpr int SMEM_HG = ST2 * (H_ASTG + H_BSTG) * 2;   // 61440 B
__global__ void __launch_bounds__(256) k_hgemm(
    const __half* __restrict__ A, int lda,
    const __half* __restrict__ B, int ldb,
    const float* __restrict__ bias,
    __half* __restrict__ C, int ldc,
    int M, int N, int K)
{
    extern __shared__ __half sm[];
    __half* AsB = sm;
    __half* BsB = sm + ST2 * H_ASTG;

    const int tid = threadIdx.x;
    const int lane = tid & 31;
    const int warpId = tid >> 5;
    const int warpM = warpId & 3;
    const int warpN = warpId >> 2;
    const int g = lane >> 2;
    const int t = lane & 3;
    const int lr16 = lane & 15;
    const int lk8 = (lane >> 4) * 8;

    const int ncol = blockIdx.x * 128;
    const int mrow = blockIdx.y * 128;

    float acc[2][8][4];
#pragma unroll
    for (int mt = 0; mt < 2; mt++)
#pragma unroll
        for (int nt = 0; nt < 8; nt++)
#pragma unroll
            for (int q = 0; q < 4; q++) acc[mt][nt][q] = 0.f;

    const int NT = K >> 5;

    auto load_tile = [&](int st, int kt) {
        int k0 = kt << 5;
        __half* As = AsB + st * H_ASTG;
        __half* Bs = BsB + st * H_BSTG;
#pragma unroll
        for (int i = 0; i < 2; i++) {
            int c = tid + i * 256;
            int m = c >> 2, kc = (c & 3) * 8;
            cp16(As + m * 40 + kc, A + (size_t)(mrow + m) * lda + k0 + kc,
                 (mrow + m) < M);
        }
#pragma unroll
        for (int i = 0; i < 2; i++) {
            int c = tid + i * 256;
            int n = c >> 2, kc = (c & 3) * 8;
            cp16(Bs + n * 40 + kc, B + (size_t)(ncol + n) * ldb + k0 + kc,
                 (ncol + n) < N);
        }
    };

#pragma unroll
    for (int p = 0; p < ST2 - 1; p++) {
        if (p < NT) load_tile(p, p);
        CP_COMMIT();
    }

    for (int kt = 0; kt < NT; kt++) {
        int st = kt % ST2;
        if (kt + ST2 - 1 < NT) load_tile((kt + ST2 - 1) % ST2, kt + ST2 - 1);
        CP_COMMIT();
        asm volatile("cp.async.wait_group %0;\n" :: "n"(ST2 - 1) : "memory");
        __syncthreads();

        const __half* As = AsB + st * H_ASTG;
        const __half* Bs = BsB + st * H_BSTG;
#pragma unroll
        for (int ks = 0; ks < 32; ks += 16) {
            uint32_t afr[2][4], bfr[8][2];
#pragma unroll
            for (int mt = 0; mt < 2; mt++) {
                ldsm_x4(afr[mt][0], afr[mt][1], afr[mt][2], afr[mt][3],
                        smem_u32(As + (warpM * 32 + mt * 16 + lr16) * 40 + ks + lk8));
            }
#pragma unroll
            for (int ntp = 0; ntp < 4; ntp++) {
                uint32_t q0, q1, q2, q3;
                ldsm_x4(q0, q1, q2, q3,
                        smem_u32(Bs + (warpN * 64 + ntp * 16 + lr16) * 40 + ks + lk8));
                bfr[2 * ntp][0]     = q0;
                bfr[2 * ntp + 1][0] = q1;
                bfr[2 * ntp][1]     = q2;
                bfr[2 * ntp + 1][1] = q3;
            }
#pragma unroll
            for (int mt = 0; mt < 2; mt++)
#pragma unroll
                for (int nt = 0; nt < 8; nt++)
                    mma_f16(acc[mt][nt], afr[mt], bfr[nt]);
        }
        __syncthreads();
    }

#pragma unroll
    for (int mt = 0; mt < 2; mt++) {
#pragma unroll
        for (int nt = 0; nt < 8; nt++) {
            int m0 = mrow + warpM * 32 + mt * 16 + g;
            int n0 = ncol + warpN * 64 + nt * 8 + 2 * t;
            if (n0 < N) {
                float b0 = bias[n0], b1 = bias[n0 + 1];
                if (m0 < M) {
                    __half2 h01 = __floats2half2_rn(acc[mt][nt][0] + b0,
                                                    acc[mt][nt][1] + b1);
                    *(uint32_t*)&C[(size_t)m0 * ldc + n0] = *(uint32_t*)&h01;
                }
                if (m0 + 8 < M) {
                    __half2 h23 = __floats2half2_rn(acc[mt][nt][2] + b0,
                                                    acc[mt][nt][3] + b1);
                    *(uint32_t*)&C[(size_t)(m0 + 8) * ldc + n0] = *(uint32_t*)&h23;
                }
            }
        }
    }
}

// -------------------- fused gates GEMM: G2 (by<31) + G1 (by==31) -------------
// by < 31:  g2[by*64 .. +64) = E @ wih2^T          (K=320, raw store)
// by == 31: g1[0..64)        = Xp @ wih1^T + bias2 (K=256)
// All M/N extents exact -> no guards. 64x128 tile, 4-stage cp.async pipeline.
constexpr int ST4 = 4;
constexpr int H64_ASTG = 64 * 40;
constexpr int H64_BSTG = 128 * 40;
constexpr int SMEM_HG64 = ST4 * (H64_ASTG + H64_BSTG) * 2;   // 61440 B
__global__ void __launch_bounds__(256) k_gates(
    const __half* __restrict__ E, const __half* __restrict__ wih2,
    const __half* __restrict__ xph, const __half* __restrict__ wih1,
    const float* __restrict__ bias2,
    float* __restrict__ g2, float* __restrict__ g1)
{
    extern __shared__ __half sm[];
    __half* AsB = sm;
    __half* BsB = sm + ST4 * H64_ASTG;

    const int tid = threadIdx.x;
    const int lane = tid & 31;
    const int warpId = tid >> 5;
    const int warpM = warpId & 1;
    const int warpN = warpId >> 1;
    const int g = lane >> 2;
    const int t = lane & 3;
    const int lr16 = lane & 15;
    const int lk8 = (lane >> 4) * 8;

    const int ncol = blockIdx.x * 128;
    const bool isG1 = (blockIdx.y == 31);
    const __half* A  = isG1 ? xph : E + (size_t)blockIdx.y * 64 * KE;
    const __half* B  = isG1 ? wih1 : wih2;
    const int lda    = isG1 ? HH : KE;
    const int K      = isG1 ? HH : KE;
    float* C         = isG1 ? g1 : g2 + (size_t)blockIdx.y * 64 * GG;

    float acc[2][4][4];
#pragma unroll
    for (int mt = 0; mt < 2; mt++)
#pragma unroll
        for (int nt = 0; nt < 4; nt++)
#pragma unroll
            for (int q = 0; q < 4; q++) acc[mt][nt][q] = 0.f;

    const int NT = K >> 5;

    auto load_tile = [&](int st, int kt) {
        int k0 = kt << 5;
        __half* As = AsB + st * H64_ASTG;
        __half* Bs = BsB + st * H64_BSTG;
        {
            int m = tid >> 2, kc = (tid & 3) * 8;
            cp16(As + m * 40 + kc, A + (size_t)m * lda + k0 + kc, true);
        }
#pragma unroll
        for (int i = 0; i < 2; i++) {
            int c = tid + i * 256;
            int n = c >> 2, kc = (c & 3) * 8;
            cp16(Bs + n * 40 + kc, B + (size_t)(ncol + n) * lda + k0 + kc, true);
        }
    };

#pragma unroll
    for (int p = 0; p < ST4 - 1; p++) {
        if (p < NT) load_tile(p, p);
        CP_COMMIT();
    }

    for (int kt = 0; kt < NT; kt++) {
        int st = kt % ST4;
        if (kt + ST4 - 1 < NT) load_tile((kt + ST4 - 1) % ST4, kt + ST4 - 1);
        CP_COMMIT();
        asm volatile("cp.async.wait_group %0;\n" :: "n"(ST4 - 1) : "memory");
        __syncthreads();

        const __half* As = AsB + st * H64_ASTG;
        const __half* Bs = BsB + st * H64_BSTG;
#pragma unroll
        for (int ks = 0; ks < 32; ks += 16) {
            uint32_t afr[2][4], bfr[4][2];
#pragma unroll
            for (int mt = 0; mt < 2; mt++) {
                ldsm_x4(afr[mt][0], afr[mt][1], afr[mt][2], afr[mt][3],
                        smem_u32(As + (warpM * 32 + mt * 16 + lr16) * 40 + ks + lk8));
            }
#pragma unroll
            for (int ntp = 0; ntp < 2; ntp++) {
                uint32_t q0, q1, q2, q3;
                ldsm_x4(q0, q1, q2, q3,
                        smem_u32(Bs + (warpN * 32 + ntp * 16 + lr16) * 40 + ks + lk8));
                bfr[2 * ntp][0]     = q0;
                bfr[2 * ntp + 1][0] = q1;
                bfr[2 * ntp][1]     = q2;
                bfr[2 * ntp + 1][1] = q3;
            }
#pragma unroll
            for (int mt = 0; mt < 2; mt++)
#pragma unroll
                for (int nt = 0; nt < 4; nt++)
                    mma_f16(acc[mt][nt], afr[mt], bfr[nt]);
        }
        __syncthreads();
    }

#pragma unroll
    for (int mt = 0; mt < 2; mt++) {
#pragma unroll
        for (int nt = 0; nt < 4; nt++) {
            int m0 = warpM * 32 + mt * 16 + g;
            int n0 = ncol + warpN * 32 + nt * 8 + 2 * t;
            float b0 = 0.f, b1 = 0.f;
            if (isG1) { b0 = bias2[n0]; b1 = bias2[n0 + 1]; }
            C[(size_t)m0 * GG + n0]           = acc[mt][nt][0] + b0;
            C[(size_t)m0 * GG + n0 + 1]       = acc[mt][nt][1] + b1;
            C[(size_t)(m0 + 8) * GG + n0]     = acc[mt][nt][2] + b0;
            C[(size_t)(m0 + 8) * GG + n0 + 1] = acc[mt][nt][3] + b1;
        }
    }
}

// -------------------- recurrence: 4 clusters x 8 CTAs ------------------------
// Per-step gates = h@w_hh^T (TC) + G2[step row] + G1[batch row] (G1 preloaded
// into registers once — step-invariant).
__global__ void __launch_bounds__(256, 1) __cluster_dims__(8, 1, 1)
k_rec(const float* __restrict__ w_hh) {
    __shared__ __align__(16) __half hs[16][264];
    __shared__ float gbuf[16][132];

    const int tid = threadIdx.x;
    const int lane = tid & 31;
    const int wid = tid >> 5;
    const int g = lane >> 2;
    const int t = lane & 3;
    const int lr16 = lane & 15;
    const int lk8 = (lane >> 4) * 8;
    const int rank = blockIdx.x & 7;
    const int grp = blockIdx.x >> 3;
    const int j0 = rank * 32;
    const int brow0 = grp * 16;

    uint32_t wb[2][16][2];
#pragma unroll
    for (int nt = 0; nt < 2; nt++) {
        int lc = wid * 16 + nt * 8 + g;
        int wrow = (lc >> 5) * 256 + j0 + (lc & 31);
        const float* wr = w_hh + (size_t)wrow * HH;
#pragma unroll
        for (int kt = 0; kt < 16; kt++) {
            __half2 h0 = __floats2half2_rn(wr[kt * 16 + 2 * t], wr[kt * 16 + 2 * t + 1]);
            __half2 h1 = __floats2half2_rn(wr[kt * 16 + 2 * t + 8], wr[kt * 16 + 2 * t + 9]);
            wb[nt][kt][0] = *(uint32_t*)&h0;
            wb[nt][kt][1] = *(uint32_t*)&h1;
        }
    }

    float creg[2] = {0.f, 0.f};
    const int crow = tid >> 4;
    const int cj2 = (tid & 15) * 2;
    int lc0[2], r0[2];
#pragma unroll
    for (int nt = 0; nt < 2; nt++) {
        lc0[nt] = wid * 16 + nt * 8 + 2 * t;
        r0[nt] = (lc0[nt] >> 5) * 256 + j0 + (lc0[nt] & 31);
    }

    // preload step-invariant G1 values (8 floats)
    float2 p0[2], p1[2];
#pragma unroll
    for (int nt = 0; nt < 2; nt++) {
        p0[nt] = *(const float2*)&d_g1[(size_t)(brow0 + g) * GG + r0[nt]];
        p1[nt] = *(const float2*)&d_g1[(size_t)(brow0 + g + 8) * GG + r0[nt]];
    }

    for (int s = 0; s < SS; s++) {
        const float* gp = d_g2 + ((size_t)s * BB + brow0) * GG;
        float2 q0[2], q1[2];
#pragma unroll
        for (int nt = 0; nt < 2; nt++) {
            q0[nt] = *(const float2*)&gp[(size_t)g * GG + r0[nt]];
            q1[nt] = *(const float2*)&gp[(size_t)(g + 8) * GG + r0[nt]];
        }

        float accA[2][4] = {{0.f, 0.f, 0.f, 0.f}, {0.f, 0.f, 0.f, 0.f}};
        float accB[2][4] = {{0.f, 0.f, 0.f, 0.f}, {0.f, 0.f, 0.f, 0.f}};

        if (s > 0) {
            const uint4* src = (const uint4*)(d_Hall + ((size_t)(s - 1) * BB + brow0) * HH);
#pragma unroll
            for (int i = 0; i < 2; i++) {
                int c = tid + i * 256;
                int m = c >> 5, kc = c & 31;
                *(uint4*)&hs[m][kc * 8] = src[m * 32 + kc];
            }
            __syncthreads();
#pragma unroll
            for (int kt = 0; kt < 16; kt++) {
                uint32_t af[4];
                ldsm_x4(af[0], af[1], af[2], af[3],
                        smem_u32(&hs[lr16][kt * 16 + lk8]));
                float* d0 = (kt < 8) ? accA[0] : accB[0];
                float* d1 = (kt < 8) ? accA[1] : accB[1];
                mma_f16(d0, af, wb[0][kt]);
                mma_f16(d1, af, wb[1][kt]);
            }
        }

#pragma unroll
        for (int nt = 0; nt < 2; nt++) {
            gbuf[g][lc0[nt]]         = accA[nt][0] + accB[nt][0] + q0[nt].x + p0[nt].x;
            gbuf[g][lc0[nt] + 1]     = accA[nt][1] + accB[nt][1] + q0[nt].y + p0[nt].y;
            gbuf[g + 8][lc0[nt]]     = accA[nt][2] + accB[nt][2] + q1[nt].x + p1[nt].x;
            gbuf[g + 8][lc0[nt] + 1] = accA[nt][3] + accB[nt][3] + q1[nt].y + p1[nt].y;
        }
        __syncthreads();

        {
            float hv[2];
#pragma unroll
            for (int e = 0; e < 2; e++) {
                int jj = cj2 + e;
                float gi = gbuf[crow][jj],      gf = gbuf[crow][32 + jj];
                float gc = gbuf[crow][64 + jj], go = gbuf[crow][96 + jj];
                float ii = fast_sigmoid(gi);
                float ff = fast_sigmoid(gf);
                float gv = fast_tanh(gc);
                float oo = fast_sigmoid(go);
                float cn = ff * creg[e] + ii * gv;
                creg[e] = cn;
                hv[e] = oo * fast_tanh(cn);
            }
            __half2 hp = __floats2half2_rn(hv[0], hv[1]);
            *(uint32_t*)&d_Hall[((size_t)s * BB + brow0 + crow) * HH + j0 + cj2] =
                *(uint32_t*)&hp;
        }

        if (s + 1 < SS) {
            asm volatile("barrier.cluster.arrive.aligned;" ::: "memory");
            asm volatile("barrier.cluster.wait.aligned;" ::: "memory");
        }
    }
}

// -------------------- fused one-hot + log-softmax (register-cached row) ------
constexpr int V8 = VV / 8;   // 1250 uint4 groups
__global__ void __launch_bounds__(256) k_softmax(float* __restrict__ out) {
    const int r = blockIdx.x;
    const int tid = threadIdx.x;
    if (r >= MROWS) {
        int b = r - MROWS;
        float* dst = out + (size_t)b * TT * VV;
        for (int v = tid * 4; v < VV; v += 1024) {
            float4 z = make_float4(0.f, 0.f, 0.f, 0.f);
            if (v == 0) z.y = 1.f;         // index 1 = START_ID
            __stcs((float4*)(dst + v), z);
        }
        return;
    }
    const int s = r >> 6, b = r & 63;
    const uint4* src = (const uint4*)(d_logits + (size_t)r * VV);

    uint4 vals[5];
    float m = -1e30f, sum = 0.f;
#pragma unroll
    for (int i = 0; i < 5; i++) {
        int c = tid + i * 256;
        if (c < V8) {
            uint4 u = src[c];
            vals[i] = u;
            float2 f0 = __half22float2(*(__half2*)&u.x);
            float2 f1 = __half22float2(*(__half2*)&u.y);
            float2 f2 = __half22float2(*(__half2*)&u.z);
            float2 f3 = __half22float2(*(__half2*)&u.w);
            float m8 = fmaxf(fmaxf(fmaxf(f0.x, f0.y), fmaxf(f1.x, f1.y)),
                             fmaxf(fmaxf(f2.x, f2.y), fmaxf(f3.x, f3.y)));
            if (m8 > m) { sum *= __expf(m - m8); m = m8; }
            sum += __expf(f0.x - m) + __expf(f0.y - m)
                 + __expf(f1.x - m) + __expf(f1.y - m)
                 + __expf(f2.x - m) + __expf(f2.y - m)
                 + __expf(f3.x - m) + __expf(f3.y - m);
        }
    }
#pragma unroll
    for (int o = 16; o; o >>= 1) {
        float mo = __shfl_xor_sync(0xffffffffu, m, o);
        float so = __shfl_xor_sync(0xffffffffu, sum, o);
        float M = fmaxf(m, mo);
        sum = sum * __expf(m - M) + so * __expf(mo - M);
        m = M;
    }
    __shared__ float sm_m[8], sm_s[8], s_lz;
    if ((tid & 31) == 0) { sm_m[tid >> 5] = m; sm_s[tid >> 5] = sum; }
    __syncthreads();
    if (tid == 0) {
        float M = sm_m[0], S = sm_s[0];
#pragma unroll
        for (int w = 1; w < 8; w++) {
            float mo = sm_m[w], so = sm_s[w];
            float MM = fmaxf(M, mo);
            S = S * __expf(M - MM) + so * __expf(mo - MM);
            M = MM;
        }
        s_lz = M + logf(S);
    }
    __syncthreads();
    const float lz = s_lz;
    float4* dst = (float4*)(out + ((size_t)b * TT + s + 1) * VV);
#pragma unroll
    for (int i = 0; i < 5; i++) {
        int c = tid + i * 256;
        if (c < V8) {
            uint4 u = vals[i];
            float2 f0 = __half22float2(*(__half2*)&u.x);
            float2 f1 = __half22float2(*(__half2*)&u.y);
            float2 f2 = __half22float2(*(__half2*)&u.z);
            float2 f3 = __half22float2(*(__half2*)&u.w);
            __stcs(&dst[2 * c],
                   make_float4(f0.x - lz, f0.y - lz, f1.x - lz, f1.y - lz));
            __stcs(&dst[2 * c + 1],
                   make_float4(f2.x - lz, f2.y - lz, f3.x - lz, f3.y - lz));
        }
    }
}

// -------------------- launch ------------------------------------------------
extern "C" void kernel_launch(void* const* d_in, const int* in_sizes, int n_in,
                              void* d_out, int out_size) {
    const float* X    = (const float*)d_in[0];
    const float* emb  = (const float*)d_in[1];
    const float* fc1w = (const float*)d_in[2];
    const float* fc1b = (const float*)d_in[3];
    const float* wih  = (const float*)d_in[4];
    const float* whh  = (const float*)d_in[5];
    const float* bih  = (const float*)d_in[6];
    const float* bhh  = (const float*)d_in[7];
    const float* fc2w = (const float*)d_in[8];
    const float* fc2b = (const float*)d_in[9];
    const int*   lab  = (const int*)d_in[10];
    float* out = (float*)d_out;

    __half *pXph, *pE, *pHall, *pW2h, *pWih1, *pWih2, *pLogits;
    float *pBias2, *pG1, *pG2;
    cudaGetSymbolAddress((void**)&pXph,    d_xph);
    cudaGetSymbolAddress((void**)&pE,      d_E);
    cudaGetSymbolAddress((void**)&pBias2,  d_bias2);
    cudaGetSymbolAddress((void**)&pG1,     d_g1);
    cudaGetSymbolAddress((void**)&pG2,     d_g2);
    cudaGetSymbolAddress((void**)&pHall,   d_Hall);
    cudaGetSymbolAddress((void**)&pLogits, d_logits);
    cudaGetSymbolAddress((void**)&pW2h,    d_w2h);
    cudaGetSymbolAddress((void**)&pWih1,   d_wih1h);
    cudaGetSymbolAddress((void**)&pWih2,   d_wih2h);

    static int attr_set = 0;
    if (!attr_set) {
        cudaFuncSetAttribute(k_hgemm,
                             cudaFuncAttributeMaxDynamicSharedMemorySize, SMEM_HG);
        cudaFuncSetAttribute(k_gates,
                             cudaFuncAttributeMaxDynamicSharedMemorySize, SMEM_HG64);
        attr_set = 1;
    }

    k_fc1<<<dim3(8, 16), 256>>>(X, fc1w);
    k_fc1red<<<18, 256>>>(fc1b, lab, bih, bhh);
    k_cvtall<<<RALL / 256, 256>>>(emb, wih, fc2w);

    // gates: G2 (248 CTAs, K=320) + G1 (8 CTAs, K=256) in one launch
    k_gates<<<dim3(8, 32), 256, SMEM_HG64>>>(pE, pWih2, pXph, pWih1, pBias2,
                                             pG2, pG1);

    // recurrence: 32 CTAs = 4 clusters x 8 (cluster barrier between steps)
    k_rec<<<32, 256>>>(whh);

    // fc2: logits[1984,10000] (fp16) = Hall @ w2h^T + fc2b, 3-stage pipeline
    k_hgemm<<<dim3(79, 16), 256, SMEM_HG>>>(pHall, HH, pW2h, HH, fc2b,
                                            pLogits, VV, MROWS, VV, HH);

    k_softmax<<<MROWS + BB, 256>>>(out);
}

// round 16
// speedup vs baseline: 1.0853x; 1.0499x over previous
#include <cuda_runtime.h>
#include <cuda_fp16.h>
#include <math.h>
#include <stdint.h>

// Problem dims
constexpr int BB = 64;
constexpr int TT = 32;
constexpr int SS = 31;     // scan steps (T-1)
constexpr int VV = 10000;
constexpr int EE = 300;
constexpr int HH = 256;
constexpr int FF = 4096;
constexpr int GG = 1024;   // 4*H
constexpr int KIN = HH + EE;   // 556
constexpr int KE = 320;        // EE padded to 64-multiple
constexpr int MROWS = SS * BB; // 1984

// -------------------- device scratch (static, no allocs) --------------------
__device__ float  d_xpart[16 * BB * HH];
__device__ __half d_xph[BB * HH];          // Xp fp16 (G1 A-matrix)
__device__ __half d_E[MROWS * KE];         // gathered embeddings fp16, padded
__device__ float  d_bias2[GG];             // b_ih + b_hh
__device__ float  d_g1[BB * GG];           // Xp @ wih1^T + bias2
__device__ float  d_g2[MROWS * GG];        // E @ wih2^T (no bias)
__device__ __half d_Hall[MROWS * HH];      // h history fp16 (fc2 A matrix)
__device__ __half d_logits[MROWS * VV];    // fc2 output, fp16 (40 MB)
__device__ int    d_labels[TT * BB];
__device__ __half d_w2h[VV * HH];          // fc2_w fp16
__device__ __half d_wih1h[GG * HH];        // w_ih cols [0,256) fp16
__device__ __half d_wih2h[GG * KE];        // w_ih cols [256,556) fp16, padded

// -------------------- helpers ------------------------------------------------
__device__ __forceinline__ uint32_t smem_u32(const void* p) {
    return (uint32_t)__cvta_generic_to_shared(p);
}
__device__ __forceinline__ void cp16(void* smem_dst, const void* gsrc, bool pred) {
    uint32_t saddr = smem_u32(smem_dst);
    int sz = pred ? 16 : 0;
    asm volatile("cp.async.cg.shared.global [%0], [%1], 16, %2;\n"
                 :: "r"(saddr), "l"(gsrc), "r"(sz) : "memory");
}
__device__ __forceinline__ void mma_f16(float* d, const uint32_t* a, const uint32_t* b) {
    asm volatile(
        "mma.sync.aligned.m16n8k16.row.col.f32.f16.f16.f32 "
        "{%0,%1,%2,%3}, {%4,%5,%6,%7}, {%8,%9}, {%0,%1,%2,%3};"
        : "+f"(d[0]), "+f"(d[1]), "+f"(d[2]), "+f"(d[3])
        : "r"(a[0]), "r"(a[1]), "r"(a[2]), "r"(a[3]), "r"(b[0]), "r"(b[1]));
}
__device__ __forceinline__ void ldsm_x4(uint32_t& r0, uint32_t& r1,
                                        uint32_t& r2, uint32_t& r3, uint32_t addr) {
    asm volatile("ldmatrix.sync.aligned.m8n8.x4.shared.b16 {%0,%1,%2,%3}, [%4];"
                 : "=r"(r0), "=r"(r1), "=r"(r2), "=r"(r3) : "r"(addr));
}
__device__ __forceinline__ uint2 pack_h4(float4 v) {
    __half2 p0 = __floats2half2_rn(v.x, v.y);
    __half2 p1 = __floats2half2_rn(v.z, v.w);
    uint2 u;
    u.x = *(uint32_t*)&p0;
    u.y = *(uint32_t*)&p1;
    return u;
}
__device__ __forceinline__ float fast_tanh(float x) {
    float r;
    asm("tanh.approx.f32 %0, %1;" : "=f"(r) : "f"(x));
    return r;
}
__device__ __forceinline__ float fast_sigmoid(float x) {
    return 1.f / (1.f + __expf(-x));
}
#define CP_COMMIT() asm volatile("cp.async.commit_group;\n" ::: "memory")

// -------------------- fc1: Xp = X @ fc1_w.T + b (split-K SIMT) ---------------
__global__ void __launch_bounds__(256) k_fc1(const float* __restrict__ X,
                                             const float* __restrict__ W) {
    const int h0 = blockIdx.x * 32;
    const int kb = blockIdx.y;
    const int kbase = kb * 256;
    const int tid = threadIdx.x;
    __shared__ __align__(16) float Xs[32][68];
    __shared__ float Wsh[32][33];
    float acc[4][2];
#pragma unroll
    for (int q = 0; q < 4; q++) { acc[q][0] = 0.f; acc[q][1] = 0.f; }
    const int tb = (tid & 15) * 4;
    const int th = (tid >> 4) * 2;

    for (int t = 0; t < 8; t++) {
        int k0 = kbase + t * 32;
#pragma unroll
        for (int i = 0; i < 8; i++) {
            int idx = tid + i * 256;
            int b = idx >> 5, kk = idx & 31;
            Xs[kk][b] = X[(size_t)b * FF + k0 + kk];
        }
#pragma unroll
        for (int i = 0; i < 4; i++) {
            int idx = tid + i * 256;
            int hh = idx >> 5, kk = idx & 31;
            Wsh[kk][hh] = W[(size_t)(h0 + hh) * FF + k0 + kk];
        }
        __syncthreads();
#pragma unroll
        for (int kk = 0; kk < 32; kk++) {
            float4 x4 = *(const float4*)&Xs[kk][tb];
            float w0 = Wsh[kk][th], w1 = Wsh[kk][th + 1];
            acc[0][0] += x4.x * w0; acc[0][1] += x4.x * w1;
            acc[1][0] += x4.y * w0; acc[1][1] += x4.y * w1;
            acc[2][0] += x4.z * w0; acc[2][1] += x4.z * w1;
            acc[3][0] += x4.w * w0; acc[3][1] += x4.w * w1;
        }
        __syncthreads();
    }
#pragma unroll
    for (int q = 0; q < 4; q++)
#pragma unroll
        for (int j = 0; j < 2; j++)
            d_xpart[kb * (BB * HH) + (tb + q) * HH + h0 + th + j] = acc[q][j];
}

// -------------------- fc1 reduce (fp16 out) + labels + bias2 -----------------
__global__ void k_fc1red(const float* __restrict__ fc1_b,
                         const int* __restrict__ lab,
                         const float* __restrict__ bih,
                         const float* __restrict__ bhh) {
    const int blk = blockIdx.x;
    const int tid = threadIdx.x;
    if (blk < 16) {
        int i4 = blk * 256 + tid;
        const float4* bp = (const float4*)fc1_b;
        float4 s = bp[i4 & 63];
#pragma unroll
        for (int kb = 0; kb < 16; kb++) {
            float4 p = ((const float4*)(d_xpart + kb * BB * HH))[i4];
            s.x += p.x; s.y += p.y; s.z += p.z; s.w += p.w;
        }
        ((uint2*)d_xph)[i4] = pack_h4(s);
    } else if (blk == 16) {
        __shared__ int is64;
        if (tid == 0) {
            int f = 1;
            for (int i = 1; i < 64 && f; i += 2)
                if (lab[i] != 0) f = 0;
            is64 = f;
        }
        __syncthreads();
        for (int i = tid; i < TT * BB; i += 256)
            d_labels[i] = is64 ? (int)(((const long long*)lab)[i]) : lab[i];
    } else {
        for (int i = tid; i < GG; i += 256)
            d_bias2[i] = bih[i] + bhh[i];
    }
}

// -------------------- merged elementwise: E + wih1 + wih2 + fc2w -------------
constexpr int E4 = KE / 4;                  // 80 groups per E row
constexpr int RE  = MROWS * E4;             // 158720
constexpr int RW1 = GG * (HH / 4);          // 65536
constexpr int RW2 = GG * E4;                // 81920
constexpr int R3  = VV * HH / 4;            // 640000
constexpr int RALL = RE + RW1 + RW2 + R3;   // 946176
__global__ void __launch_bounds__(256) k_cvtall(const float* __restrict__ emb_table,
                                                const float* __restrict__ wih,
                                                const float* __restrict__ fc2w) {
    int idx = blockIdx.x * 256 + threadIdx.x;
    if (idx < RE) {                         // E = gathered embeddings, padded
        int r = idx / E4, c = idx - r * E4;
        int s = r >> 6, b = r & 63;
        float4 v = make_float4(0.f, 0.f, 0.f, 0.f);
        if (c < 75) {                       // 75*4 = 300 = EE exactly
            int tok = (s == 0) ? 1 : d_labels[s * BB + b];   // START_ID = 1
            v = *(const float4*)(emb_table + (size_t)tok * EE + c * 4);
        }
        ((uint2*)d_E)[idx] = pack_h4(v);
    } else if (idx < RE + RW1) {            // wih cols [0,256)
        int i = idx - RE;
        int r = i >> 6, c = i & 63;
        float4 v = *(const float4*)(wih + (size_t)r * KIN + c * 4);
        ((uint2*)d_wih1h)[i] = pack_h4(v);
    } else if (idx < RE + RW1 + RW2) {      // wih cols [256,556), padded
        int i = idx - (RE + RW1);
        int r = i / E4, c = i - r * E4;
        float4 v = (c < 75) ? *(const float4*)(wih + (size_t)r * KIN + HH + c * 4)
                            : make_float4(0.f, 0.f, 0.f, 0.f);
        ((uint2*)d_wih2h)[i] = pack_h4(v);
    } else if (idx < RALL) {                // fc2_w -> fp16
        int i = idx - (RE + RW1 + RW2);
        ((uint2*)d_w2h)[i] = pack_h4(((const float4*)fc2w)[i]);
    }
}

// -------------------- fp16 TC GEMM, 128x128 tile, BK=64, 2-stage (fc2) -------
// Halved k-iteration count: one wait_group + 2 barriers now amortize over
// 32 mma per warp instead of 16.
constexpr int ST2 = 2;
constexpr int H_ASTG = 128 * 72;                 // halves per A stage
constexpr int H_BSTG = 128 * 72;
constexpr int SMEM_HG = ST2 * (H_ASTG + H_BSTG) * 2;   // 73728 B
__global__ void __launch_bounds__(256) k_hgemm(
    const __half* __restrict__ A, int lda,
    const __half* __restrict__ B, int ldb,
    const float* __restrict__ bias,
    __half* __restrict__ C, int ldc,
    int M, int N, int K)
{
    extern __shared__ __half sm[];
    __half* AsB = sm;
    __half* BsB = sm + ST2 * H_ASTG;

    const int tid = threadIdx.x;
    const int lane = tid & 31;
    const int warpId = tid >> 5;
    const int warpM = warpId & 3;
    const int warpN = warpId >> 2;
    const int g = lane >> 2;
    const int t = lane & 3;
    const int lr16 = lane & 15;
    const int lk8 = (lane >> 4) * 8;

    const int ncol = blockIdx.x * 128;
    const int mrow = blockIdx.y * 128;

    float acc[2][8][4];
#pragma unroll
    for (int mt = 0; mt < 2; mt++)
#pragma unroll
        for (int nt = 0; nt < 8; nt++)
#pragma unroll
            for (int q = 0; q < 4; q++) acc[mt][nt][q] = 0.f;

    const int NT = K >> 6;

    auto load_tile = [&](int st, int kt) {
        int k0 = kt << 6;
        __half* As = AsB + st * H_ASTG;
        __half* Bs = BsB + st * H_BSTG;
#pragma unroll
        for (int i = 0; i < 4; i++) {
            int c = tid + i * 256;           // 0..1023
            int m = c >> 3, kc = (c & 7) * 8;
            cp16(As + m * 72 + kc, A + (size_t)(mrow + m) * lda + k0 + kc,
                 (mrow + m) < M);
        }
#pragma unroll
        for (int i = 0; i < 4; i++) {
            int c = tid + i * 256;
            int n = c >> 3, kc = (c & 7) * 8;
            cp16(Bs + n * 72 + kc, B + (size_t)(ncol + n) * ldb + k0 + kc,
                 (ncol + n) < N);
        }
    };

    load_tile(0, 0);
    CP_COMMIT();

    for (int kt = 0; kt < NT; kt++) {
        int st = kt & 1;
        if (kt + 1 < NT) load_tile(st ^ 1, kt + 1);
        CP_COMMIT();
        asm volatile("cp.async.wait_group 1;\n" ::: "memory");
        __syncthreads();

        const __half* As = AsB + st * H_ASTG;
        const __half* Bs = BsB + st * H_BSTG;
#pragma unroll
        for (int ks = 0; ks < 64; ks += 16) {
            uint32_t afr[2][4], bfr[8][2];
#pragma unroll
            for (int mt = 0; mt < 2; mt++) {
                ldsm_x4(afr[mt][0], afr[mt][1], afr[mt][2], afr[mt][3],
                        smem_u32(As + (warpM * 32 + mt * 16 + lr16) * 72 + ks + lk8));
            }
#pragma unroll
            for (int ntp = 0; ntp < 4; ntp++) {
                uint32_t q0, q1, q2, q3;
                ldsm_x4(q0, q1, q2, q3,
                        smem_u32(Bs + (warpN * 64 + ntp * 16 + lr16) * 72 + ks + lk8));
                bfr[2 * ntp][0]     = q0;
                bfr[2 * ntp + 1][0] = q1;
                bfr[2 * ntp][1]     = q2;
                bfr[2 * ntp + 1][1] = q3;
            }
#pragma unroll
            for (int mt = 0; mt < 2; mt++)
#pragma unroll
                for (int nt = 0; nt < 8; nt++)
                    mma_f16(acc[mt][nt], afr[mt], bfr[nt]);
        }
        __syncthreads();
    }

#pragma unroll
    for (int mt = 0; mt < 2; mt++) {
#pragma unroll
        for (int nt = 0; nt < 8; nt++) {
            int m0 = mrow + warpM * 32 + mt * 16 + g;
            int n0 = ncol + warpN * 64 + nt * 8 + 2 * t;
            if (n0 < N) {
                float b0 = bias[n0], b1 = bias[n0 + 1];
                if (m0 < M) {
                    __half2 h01 = __floats2half2_rn(acc[mt][nt][0] + b0,
                                                    acc[mt][nt][1] + b1);
                    *(uint32_t*)&C[(size_t)m0 * ldc + n0] = *(uint32_t*)&h01;
                }
                if (m0 + 8 < M) {
                    __half2 h23 = __floats2half2_rn(acc[mt][nt][2] + b0,
                                                    acc[mt][nt][3] + b1);
                    *(uint32_t*)&C[(size_t)(m0 + 8) * ldc + n0] = *(uint32_t*)&h23;
                }
            }
        }
    }
}

// -------------------- fused gates GEMM: BK=64, 2-stage ------------------------
// by < 31:  g2[by*64 .. +64) = E @ wih2^T          (K=320, NT=5)
// by == 31: g1[0..64)        = Xp @ wih1^T + bias2 (K=256, NT=4)
constexpr int H64_ASTG = 64 * 72;
constexpr int H64_BSTG = 128 * 72;
constexpr int SMEM_HG64 = ST2 * (H64_ASTG + H64_BSTG) * 2;   // 55296 B
__global__ void __launch_bounds__(256) k_gates(
    const __half* __restrict__ E, const __half* __restrict__ wih2,
    const __half* __restrict__ xph, const __half* __restrict__ wih1,
    const float* __restrict__ bias2,
    float* __restrict__ g2, float* __restrict__ g1)
{
    extern __shared__ __half sm[];
    __half* AsB = sm;
    __half* BsB = sm + ST2 * H64_ASTG;

    const int tid = threadIdx.x;
    const int lane = tid & 31;
    const int warpId = tid >> 5;
    const int warpM = warpId & 1;
    const int warpN = warpId >> 1;
    const int g = lane >> 2;
    const int t = lane & 3;
    const int lr16 = lane & 15;
    const int lk8 = (lane >> 4) * 8;

    const int ncol = blockIdx.x * 128;
    const bool isG1 = (blockIdx.y == 31);
    const __half* A  = isG1 ? xph : E + (size_t)blockIdx.y * 64 * KE;
    const __half* B  = isG1 ? wih1 : wih2;
    const int lda    = isG1 ? HH : KE;
    const int K      = isG1 ? HH : KE;
    float* C         = isG1 ? g1 : g2 + (size_t)blockIdx.y * 64 * GG;

    float acc[2][4][4];
#pragma unroll
    for (int mt = 0; mt < 2; mt++)
#pragma unroll
        for (int nt = 0; nt < 4; nt++)
#pragma unroll
            for (int q = 0; q < 4; q++) acc[mt][nt][q] = 0.f;

    const int NT = K >> 6;

    auto load_tile = [&](int st, int kt) {
        int k0 = kt << 6;
        __half* As = AsB + st * H64_ASTG;
        __half* Bs = BsB + st * H64_BSTG;
#pragma unroll
        for (int i = 0; i < 2; i++) {        // A: 512 chunks
            int c = tid + i * 256;
            int m = c >> 3, kc = (c & 7) * 8;
            cp16(As + m * 72 + kc, A + (size_t)m * lda + k0 + kc, true);
        }
#pragma unroll
        for (int i = 0; i < 4; i++) {        // B: 1024 chunks
            int c = tid + i * 256;
            int n = c >> 3, kc = (c & 7) * 8;
            cp16(Bs + n * 72 + kc, B + (size_t)(ncol + n) * lda + k0 + kc, true);
        }
    };

    load_tile(0, 0);
    CP_COMMIT();

    for (int kt = 0; kt < NT; kt++) {
        int st = kt & 1;
        if (kt + 1 < NT) load_tile(st ^ 1, kt + 1);
        CP_COMMIT();
        asm volatile("cp.async.wait_group 1;\n" ::: "memory");
        __syncthreads();

        const __half* As = AsB + st * H64_ASTG;
        const __half* Bs = BsB + st * H64_BSTG;
#pragma unroll
        for (int ks = 0; ks < 64; ks += 16) {
            uint32_t afr[2][4], bfr[4][2];
#pragma unroll
            for (int mt = 0; mt < 2; mt++) {
                ldsm_x4(afr[mt][0], afr[mt][1], afr[mt][2], afr[mt][3],
                        smem_u32(As + (warpM * 32 + mt * 16 + lr16) * 72 + ks + lk8));
            }
#pragma unroll
            for (int ntp = 0; ntp < 2; ntp++) {
                uint32_t q0, q1, q2, q3;
                ldsm_x4(q0, q1, q2, q3,
                        smem_u32(Bs + (warpN * 32 + ntp * 16 + lr16) * 72 + ks + lk8));
                bfr[2 * ntp][0]     = q0;
                bfr[2 * ntp + 1][0] = q1;
                bfr[2 * ntp][1]     = q2;
                bfr[2 * ntp + 1][1] = q3;
            }
#pragma unroll
            for (int mt = 0; mt < 2; mt++)
#pragma unroll
                for (int nt = 0; nt < 4; nt++)
                    mma_f16(acc[mt][nt], afr[mt], bfr[nt]);
        }
        __syncthreads();
    }

#pragma unroll
    for (int mt = 0; mt < 2; mt++) {
#pragma unroll
        for (int nt = 0; nt < 4; nt++) {
            int m0 = warpM * 32 + mt * 16 + g;
            int n0 = ncol + warpN * 32 + nt * 8 + 2 * t;
            float b0 = 0.f, b1 = 0.f;
            if (isG1) { b0 = bias2[n0]; b1 = bias2[n0 + 1]; }
            C[(size_t)m0 * GG + n0]           = acc[mt][nt][0] + b0;
            C[(size_t)m0 * GG + n0 + 1]       = acc[mt][nt][1] + b1;
            C[(size_t)(m0 + 8) * GG + n0]     = acc[mt][nt][2] + b0;
            C[(size_t)(m0 + 8) * GG + n0 + 1] = acc[mt][nt][3] + b1;
        }
    }
}

// -------------------- recurrence: 4 clusters x 8 CTAs ------------------------
__global__ void __launch_bounds__(256, 1) __cluster_dims__(8, 1, 1)
k_rec(const float* __restrict__ w_hh) {
    __shared__ __align__(16) __half hs[16][264];
    __shared__ float gbuf[16][132];

    const int tid = threadIdx.x;
    const int lane = tid & 31;
    const int wid = tid >> 5;
    const int g = lane >> 2;
    const int t = lane & 3;
    const int lr16 = lane & 15;
    const int lk8 = (lane >> 4) * 8;
    const int rank = blockIdx.x & 7;
    const int grp = blockIdx.x >> 3;
    const int j0 = rank * 32;
    const int brow0 = grp * 16;

    uint32_t wb[2][16][2];
#pragma unroll
    for (int nt = 0; nt < 2; nt++) {
        int lc = wid * 16 + nt * 8 + g;
        int wrow = (lc >> 5) * 256 + j0 + (lc & 31);
        const float* wr = w_hh + (size_t)wrow * HH;
#pragma unroll
        for (int kt = 0; kt < 16; kt++) {
            __half2 h0 = __floats2half2_rn(wr[kt * 16 + 2 * t], wr[kt * 16 + 2 * t + 1]);
            __half2 h1 = __floats2half2_rn(wr[kt * 16 + 2 * t + 8], wr[kt * 16 + 2 * t + 9]);
            wb[nt][kt][0] = *(uint32_t*)&h0;
            wb[nt][kt][1] = *(uint32_t*)&h1;
        }
    }

    float creg[2] = {0.f, 0.f};
    const int crow = tid >> 4;
    const int cj2 = (tid & 15) * 2;
    int lc0[2], r0[2];
#pragma unroll
    for (int nt = 0; nt < 2; nt++) {
        lc0[nt] = wid * 16 + nt * 8 + 2 * t;
        r0[nt] = (lc0[nt] >> 5) * 256 + j0 + (lc0[nt] & 31);
    }

    // preload step-invariant G1 values (8 floats)
    float2 p0[2], p1[2];
#pragma unroll
    for (int nt = 0; nt < 2; nt++) {
        p0[nt] = *(const float2*)&d_g1[(size_t)(brow0 + g) * GG + r0[nt]];
        p1[nt] = *(const float2*)&d_g1[(size_t)(brow0 + g + 8) * GG + r0[nt]];
    }

    for (int s = 0; s < SS; s++) {
        const float* gp = d_g2 + ((size_t)s * BB + brow0) * GG;
        float2 q0[2], q1[2];
#pragma unroll
        for (int nt = 0; nt < 2; nt++) {
            q0[nt] = *(const float2*)&gp[(size_t)g * GG + r0[nt]];
            q1[nt] = *(const float2*)&gp[(size_t)(g + 8) * GG + r0[nt]];
        }

        float accA[2][4] = {{0.f, 0.f, 0.f, 0.f}, {0.f, 0.f, 0.f, 0.f}};
        float accB[2][4] = {{0.f, 0.f, 0.f, 0.f}, {0.f, 0.f, 0.f, 0.f}};

        if (s > 0) {
            const uint4* src = (const uint4*)(d_Hall + ((size_t)(s - 1) * BB + brow0) * HH);
#pragma unroll
            for (int i = 0; i < 2; i++) {
                int c = tid + i * 256;
                int m = c >> 5, kc = c & 31;
                *(uint4*)&hs[m][kc * 8] = src[m * 32 + kc];
            }
            __syncthreads();
#pragma unroll
            for (int kt = 0; kt < 16; kt++) {
                uint32_t af[4];
                ldsm_x4(af[0], af[1], af[2], af[3],
                        smem_u32(&hs[lr16][kt * 16 + lk8]));
                float* d0 = (kt < 8) ? accA[0] : accB[0];
                float* d1 = (kt < 8) ? accA[1] : accB[1];
                mma_f16(d0, af, wb[0][kt]);
                mma_f16(d1, af, wb[1][kt]);
            }
        }

#pragma unroll
        for (int nt = 0; nt < 2; nt++) {
            gbuf[g][lc0[nt]]         = accA[nt][0] + accB[nt][0] + q0[nt].x + p0[nt].x;
            gbuf[g][lc0[nt] + 1]     = accA[nt][1] + accB[nt][1] + q0[nt].y + p0[nt].y;
            gbuf[g + 8][lc0[nt]]     = accA[nt][2] + accB[nt][2] + q1[nt].x + p1[nt].x;
            gbuf[g + 8][lc0[nt] + 1] = accA[nt][3] + accB[nt][3] + q1[nt].y + p1[nt].y;
        }
        __syncthreads();

        {
            float hv[2];
#pragma unroll
            for (int e = 0; e < 2; e++) {
                int jj = cj2 + e;
                float gi = gbuf[crow][jj],      gf = gbuf[crow][32 + jj];
                float gc = gbuf[crow][64 + jj], go = gbuf[crow][96 + jj];
                float ii = fast_sigmoid(gi);
                float ff = fast_sigmoid(gf);
                float gv = fast_tanh(gc);
                float oo = fast_sigmoid(go);
                float cn = ff * creg[e] + ii * gv;
                creg[e] = cn;
                hv[e] = oo * fast_tanh(cn);
            }
            __half2 hp = __floats2half2_rn(hv[0], hv[1]);
            *(uint32_t*)&d_Hall[((size_t)s * BB + brow0 + crow) * HH + j0 + cj2] =
                *(uint32_t*)&hp;
        }

        if (s + 1 < SS) {
            asm volatile("barrier.cluster.arrive.aligned;" ::: "memory");
            asm volatile("barrier.cluster.wait.aligned;" ::: "memory");
        }
    }
}

// -------------------- fused one-hot + log-softmax (register-cached row) ------
constexpr int V8 = VV / 8;   // 1250 uint4 groups
__global__ void __launch_bounds__(256) k_softmax(float* __restrict__ out) {
    const int r = blockIdx.x;
    const int tid = threadIdx.x;
    if (r >= MROWS) {
        int b = r - MROWS;
        float* dst = out + (size_t)b * TT * VV;
        for (int v = tid * 4; v < VV; v += 1024) {
            float4 z = make_float4(0.f, 0.f, 0.f, 0.f);
            if (v == 0) z.y = 1.f;         // index 1 = START_ID
            __stcs((float4*)(dst + v), z);
        }
        return;
    }
    const int s = r >> 6, b = r & 63;
    const uint4* src = (const uint4*)(d_logits + (size_t)r * VV);

    uint4 vals[5];
    float m = -1e30f, sum = 0.f;
#pragma unroll
    for (int i = 0; i < 5; i++) {
        int c = tid + i * 256;
        if (c < V8) {
            uint4 u = src[c];
            vals[i] = u;
            float2 f0 = __half22float2(*(__half2*)&u.x);
            float2 f1 = __half22float2(*(__half2*)&u.y);
            float2 f2 = __half22float2(*(__half2*)&u.z);
            float2 f3 = __half22float2(*(__half2*)&u.w);
            float m8 = fmaxf(fmaxf(fmaxf(f0.x, f0.y), fmaxf(f1.x, f1.y)),
                             fmaxf(fmaxf(f2.x, f2.y), fmaxf(f3.x, f3.y)));
            if (m8 > m) { sum *= __expf(m - m8); m = m8; }
            sum += __expf(f0.x - m) + __expf(f0.y - m)
                 + __expf(f1.x - m) + __expf(f1.y - m)
                 + __expf(f2.x - m) + __expf(f2.y - m)
                 + __expf(f3.x - m) + __expf(f3.y - m);
        }
    }
#pragma unroll
    for (int o = 16; o; o >>= 1) {
        float mo = __shfl_xor_sync(0xffffffffu, m, o);
        float so = __shfl_xor_sync(0xffffffffu, sum, o);
        float M = fmaxf(m, mo);
        sum = sum * __expf(m - M) + so * __expf(mo - M);
        m = M;
    }
    __shared__ float sm_m[8], sm_s[8], s_lz;
    if ((tid & 31) == 0) { sm_m[tid >> 5] = m; sm_s[tid >> 5] = sum; }
    __syncthreads();
    if (tid == 0) {
        float M = sm_m[0], S = sm_s[0];
#pragma unroll
        for (int w = 1; w < 8; w++) {
            float mo = sm_m[w], so = sm_s[w];
            float MM = fmaxf(M, mo);
            S = S * __expf(M - MM) + so * __expf(mo - MM);
            M = MM;
        }
        s_lz = M + logf(S);
    }
    __syncthreads();
    const float lz = s_lz;
    float4* dst = (float4*)(out + ((size_t)b * TT + s + 1) * VV);
#pragma unroll
    for (int i = 0; i < 5; i++) {
        int c = tid + i * 256;
        if (c < V8) {
            uint4 u = vals[i];
            float2 f0 = __half22float2(*(__half2*)&u.x);
            float2 f1 = __half22float2(*(__half2*)&u.y);
            float2 f2 = __half22float2(*(__half2*)&u.z);
            float2 f3 = __half22float2(*(__half2*)&u.w);
            __stcs(&dst[2 * c],
                   make_float4(f0.x - lz, f0.y - lz, f1.x - lz, f1.y - lz));
            __stcs(&dst[2 * c + 1],
                   make_float4(f2.x - lz, f2.y - lz, f3.x - lz, f3.y - lz));
        }
    }
}

// -------------------- launch ------------------------------------------------
extern "C" void kernel_launch(void* const* d_in, const int* in_sizes, int n_in,
                              void* d_out, int out_size) {
    const float* X    = (const float*)d_in[0];
    const float* emb  = (const float*)d_in[1];
    const float* fc1w = (const float*)d_in[2];
    const float* fc1b = (const float*)d_in[3];
    const float* wih  = (const float*)d_in[4];
    const float* whh  = (const float*)d_in[5];
    const float* bih  = (const float*)d_in[6];
    const float* bhh  = (const float*)d_in[7];
    const float* fc2w = (const float*)d_in[8];
    const float* fc2b = (const float*)d_in[9];
    const int*   lab  = (const int*)d_in[10];
    float* out = (float*)d_out;

    __half *pXph, *pE, *pHall, *pW2h, *pWih1, *pWih2, *pLogits;
    float *pBias2, *pG1, *pG2;
    cudaGetSymbolAddress((void**)&pXph,    d_xph);
    cudaGetSymbolAddress((void**)&pE,      d_E);
    cudaGetSymbolAddress((void**)&pBias2,  d_bias2);
    cudaGetSymbolAddress((void**)&pG1,     d_g1);
    cudaGetSymbolAddress((void**)&pG2,     d_g2);
    cudaGetSymbolAddress((void**)&pHall,   d_Hall);
    cudaGetSymbolAddress((void**)&pLogits, d_logits);
    cudaGetSymbolAddress((void**)&pW2h,    d_w2h);
    cudaGetSymbolAddress((void**)&pWih1,   d_wih1h);
    cudaGetSymbolAddress((void**)&pWih2,   d_wih2h);

    static int attr_set = 0;
    if (!attr_set) {
        cudaFuncSetAttribute(k_hgemm,
                             cudaFuncAttributeMaxDynamicSharedMemorySize, SMEM_HG);
        cudaFuncSetAttribute(k_gates,
                             cudaFuncAttributeMaxDynamicSharedMemorySize, SMEM_HG64);
        attr_set = 1;
    }

    k_fc1<<<dim3(8, 16), 256>>>(X, fc1w);
    k_fc1red<<<18, 256>>>(fc1b, lab, bih, bhh);
    k_cvtall<<<RALL / 256, 256>>>(emb, wih, fc2w);

    // gates: G2 (248 CTAs, K=320) + G1 (8 CTAs, K=256), BK=64
    k_gates<<<dim3(8, 32), 256, SMEM_HG64>>>(pE, pWih2, pXph, pWih1, pBias2,
                                             pG2, pG1);

    // recurrence: 32 CTAs = 4 clusters x 8 (cluster barrier between steps)
    k_rec<<<32, 256>>>(whh);

    // fc2: logits[1984,10000] (fp16) = Hall @ w2h^T + fc2b, BK=64
    k_hgemm<<<dim3(79, 16), 256, SMEM_HG>>>(pHall, HH, pW2h, HH, fc2b,
                                            pLogits, VV, MROWS, VV, HH);

    k_softmax<<<MROWS + BB, 256>>>(out);
}

// round 17
// speedup vs baseline: 1.1044x; 1.0176x over previous
#include <cuda_runtime.h>
#include <cuda_fp16.h>
#include <math.h>
#include <stdint.h>

// Problem dims
constexpr int BB = 64;
constexpr int TT = 32;
constexpr int SS = 31;     // scan steps (T-1)
constexpr int VV = 10000;
constexpr int EE = 300;
constexpr int HH = 256;
constexpr int FF = 4096;
constexpr int GG = 1024;   // 4*H
constexpr int KIN = HH + EE;   // 556
constexpr int KE = 320;        // EE padded to 64-multiple
constexpr int MROWS = SS * BB; // 1984

// -------------------- device scratch (static, no allocs) --------------------
__device__ float  d_xpart[16 * BB * HH];
__device__ __half d_xph[BB * HH];          // Xp fp16 (G1 A-matrix)
__device__ __half d_E[MROWS * KE];         // gathered embeddings fp16, padded
__device__ float  d_bias2[GG];             // b_ih + b_hh
__device__ float  d_g1[BB * GG];           // Xp @ wih1^T + bias2
__device__ float  d_g2[MROWS * GG];        // E @ wih2^T (no bias)
__device__ __half d_Hall[MROWS * HH];      // h history fp16 (fc2 A matrix)
__device__ __half d_logits[MROWS * VV];    // fc2 output, fp16 (40 MB)
__device__ __half d_w2h[VV * HH];          // fc2_w fp16
__device__ __half d_wih1h[GG * HH];        // w_ih cols [0,256) fp16
__device__ __half d_wih2h[GG * KE];        // w_ih cols [256,556) fp16, padded

// -------------------- helpers ------------------------------------------------
__device__ __forceinline__ uint32_t smem_u32(const void* p) {
    return (uint32_t)__cvta_generic_to_shared(p);
}
__device__ __forceinline__ void cp16(void* smem_dst, const void* gsrc, bool pred) {
    uint32_t saddr = smem_u32(smem_dst);
    int sz = pred ? 16 : 0;
    asm volatile("cp.async.cg.shared.global [%0], [%1], 16, %2;\n"
                 :: "r"(saddr), "l"(gsrc), "r"(sz) : "memory");
}
__device__ __forceinline__ void mma_f16(float* d, const uint32_t* a, const uint32_t* b) {
    asm volatile(
        "mma.sync.aligned.m16n8k16.row.col.f32.f16.f16.f32 "
        "{%0,%1,%2,%3}, {%4,%5,%6,%7}, {%8,%9}, {%0,%1,%2,%3};"
        : "+f"(d[0]), "+f"(d[1]), "+f"(d[2]), "+f"(d[3])
        : "r"(a[0]), "r"(a[1]), "r"(a[2]), "r"(a[3]), "r"(b[0]), "r"(b[1]));
}
__device__ __forceinline__ void ldsm_x4(uint32_t& r0, uint32_t& r1,
                                        uint32_t& r2, uint32_t& r3, uint32_t addr) {
    asm volatile("ldmatrix.sync.aligned.m8n8.x4.shared.b16 {%0,%1,%2,%3}, [%4];"
                 : "=r"(r0), "=r"(r1), "=r"(r2), "=r"(r3) : "r"(addr));
}
__device__ __forceinline__ uint2 pack_h4(float4 v) {
    __half2 p0 = __floats2half2_rn(v.x, v.y);
    __half2 p1 = __floats2half2_rn(v.z, v.w);
    uint2 u;
    u.x = *(uint32_t*)&p0;
    u.y = *(uint32_t*)&p1;
    return u;
}
__device__ __forceinline__ float fast_tanh(float x) {
    float r;
    asm("tanh.approx.f32 %0, %1;" : "=f"(r) : "f"(x));
    return r;
}
__device__ __forceinline__ float fast_sigmoid(float x) {
    return 1.f / (1.f + __expf(-x));
}
#define CP_COMMIT() asm volatile("cp.async.commit_group;\n" ::: "memory")

// -------------------- fused front: fc1 split-K + bias2 + cvtall --------------
// blocks [0,128): fc1 partials; block 128: bias2; blocks [129, 129+RALL/256):
// elementwise converts (E gather with inline int64-detection, wih1/wih2/fc2w).
constexpr int E4 = KE / 4;                  // 80 groups per E row
constexpr int RE  = MROWS * E4;             // 158720
constexpr int RW1 = GG * (HH / 4);          // 65536
constexpr int RW2 = GG * E4;                // 81920
constexpr int R3  = VV * HH / 4;            // 640000
constexpr int RALL = RE + RW1 + RW2 + R3;   // 946176
constexpr int NFRONT = 129 + RALL / 256;    // 129 + 3696 = 3825

__global__ void __launch_bounds__(256) k_front(
    const float* __restrict__ X,   const float* __restrict__ W,
    const float* __restrict__ bih, const float* __restrict__ bhh,
    const float* __restrict__ emb_table, const float* __restrict__ wih,
    const float* __restrict__ fc2w, const int* __restrict__ lab)
{
    const int blk = blockIdx.x;
    const int tid = threadIdx.x;

    if (blk < 128) {                 // ---- fc1 split-K partials ----
        __shared__ __align__(16) float Xs[32][68];
        __shared__ float Wsh[32][33];
        const int h0 = (blk & 7) * 32;
        const int kbase = (blk >> 3) * 256;
        float acc[4][2];
#pragma unroll
        for (int q = 0; q < 4; q++) { acc[q][0] = 0.f; acc[q][1] = 0.f; }
        const int tb = (tid & 15) * 4;
        const int th = (tid >> 4) * 2;

        for (int t = 0; t < 8; t++) {
            int k0 = kbase + t * 32;
#pragma unroll
            for (int i = 0; i < 8; i++) {
                int idx = tid + i * 256;
                int b = idx >> 5, kk = idx & 31;
                Xs[kk][b] = X[(size_t)b * FF + k0 + kk];
            }
#pragma unroll
            for (int i = 0; i < 4; i++) {
                int idx = tid + i * 256;
                int hh = idx >> 5, kk = idx & 31;
                Wsh[kk][hh] = W[(size_t)(h0 + hh) * FF + k0 + kk];
            }
            __syncthreads();
#pragma unroll
            for (int kk = 0; kk < 32; kk++) {
                float4 x4 = *(const float4*)&Xs[kk][tb];
                float w0 = Wsh[kk][th], w1 = Wsh[kk][th + 1];
                acc[0][0] += x4.x * w0; acc[0][1] += x4.x * w1;
                acc[1][0] += x4.y * w0; acc[1][1] += x4.y * w1;
                acc[2][0] += x4.z * w0; acc[2][1] += x4.z * w1;
                acc[3][0] += x4.w * w0; acc[3][1] += x4.w * w1;
            }
            __syncthreads();
        }
        const int kb = blk >> 3;
#pragma unroll
        for (int q = 0; q < 4; q++)
#pragma unroll
            for (int j = 0; j < 2; j++)
                d_xpart[kb * (BB * HH) + (tb + q) * HH + h0 + th + j] = acc[q][j];
        return;
    }

    if (blk == 128) {                // ---- bias2 ----
        for (int i = tid; i < GG; i += 256)
            d_bias2[i] = bih[i] + bhh[i];
        return;
    }

    // ---- elementwise converts ----
    int idx = (blk - 129) * 256 + tid;
    if (idx < RE) {                  // E gather (inline int64 detection)
        __shared__ int s_is64;
        if (tid < 32) {
            int v = lab[2 * tid + 1];               // odd words of first 32 i64
            unsigned mzero = __ballot_sync(0xffffffffu, v != 0);
            if (tid == 0) s_is64 = (mzero == 0);
        }
        __syncthreads();
        int r = idx / E4, c = idx - r * E4;
        int s = r >> 6, b = r & 63;
        float4 v = make_float4(0.f, 0.f, 0.f, 0.f);
        if (c < 75) {                // 75*4 = 300 = EE exactly
            int tok = 1;             // START_ID
            if (s != 0) {
                int li = s * BB + b;
                tok = s_is64 ? (int)(((const long long*)lab)[li]) : lab[li];
            }
            v = *(const float4*)(emb_table + (size_t)tok * EE + c * 4);
        }
        ((uint2*)d_E)[idx] = pack_h4(v);
    } else if (idx < RE + RW1) {     // wih cols [0,256)
        int i = idx - RE;
        int r = i >> 6, c = i & 63;
        float4 v = *(const float4*)(wih + (size_t)r * KIN + c * 4);
        ((uint2*)d_wih1h)[i] = pack_h4(v);
    } else if (idx < RE + RW1 + RW2) {   // wih cols [256,556), padded
        int i = idx - (RE + RW1);
        int r = i / E4, c = i - r * E4;
        float4 v = (c < 75) ? *(const float4*)(wih + (size_t)r * KIN + HH + c * 4)
                            : make_float4(0.f, 0.f, 0.f, 0.f);
        ((uint2*)d_wih2h)[i] = pack_h4(v);
    } else if (idx < RALL) {         // fc2_w -> fp16
        int i = idx - (RE + RW1 + RW2);
        ((uint2*)d_w2h)[i] = pack_h4(((const float4*)fc2w)[i]);
    }
}

// -------------------- fc1 reduce (fp16 out) ----------------------------------
__global__ void k_fc1red(const float* __restrict__ fc1_b) {
    int i4 = blockIdx.x * 256 + threadIdx.x;
    const float4* bp = (const float4*)fc1_b;
    float4 s = bp[i4 & 63];
#pragma unroll
    for (int kb = 0; kb < 16; kb++) {
        float4 p = ((const float4*)(d_xpart + kb * BB * HH))[i4];
        s.x += p.x; s.y += p.y; s.z += p.z; s.w += p.w;
    }
    ((uint2*)d_xph)[i4] = pack_h4(s);
}

// -------------------- fp16 TC GEMM, 128x128 tile, BK=64, 2-stage (fc2) -------
constexpr int ST2 = 2;
constexpr int H_ASTG = 128 * 72;
constexpr int H_BSTG = 128 * 72;
constexpr int SMEM_HG = ST2 * (H_ASTG + H_BSTG) * 2;   // 73728 B
__global__ void __launch_bounds__(256) k_hgemm(
    const __half* __restrict__ A, int lda,
    const __half* __restrict__ B, int ldb,
    const float* __restrict__ bias,
    __half* __restrict__ C, int ldc,
    int M, int N, int K)
{
    extern __shared__ __half sm[];
    __half* AsB = sm;
    __half* BsB = sm + ST2 * H_ASTG;

    const int tid = threadIdx.x;
    const int lane = tid & 31;
    const int warpId = tid >> 5;
    const int warpM = warpId & 3;
    const int warpN = warpId >> 2;
    const int g = lane >> 2;
    const int t = lane & 3;
    const int lr16 = lane & 15;
    const int lk8 = (lane >> 4) * 8;

    const int ncol = blockIdx.x * 128;
    const int mrow = blockIdx.y * 128;

    float acc[2][8][4];
#pragma unroll
    for (int mt = 0; mt < 2; mt++)
#pragma unroll
        for (int nt = 0; nt < 8; nt++)
#pragma unroll
            for (int q = 0; q < 4; q++) acc[mt][nt][q] = 0.f;

    const int NT = K >> 6;

    auto load_tile = [&](int st, int kt) {
        int k0 = kt << 6;
        __half* As = AsB + st * H_ASTG;
        __half* Bs = BsB + st * H_BSTG;
#pragma unroll
        for (int i = 0; i < 4; i++) {
            int c = tid + i * 256;
            int m = c >> 3, kc = (c & 7) * 8;
            cp16(As + m * 72 + kc, A + (size_t)(mrow + m) * lda + k0 + kc,
                 (mrow + m) < M);
        }
#pragma unroll
        for (int i = 0; i < 4; i++) {
            int c = tid + i * 256;
            int n = c >> 3, kc = (c & 7) * 8;
            cp16(Bs + n * 72 + kc, B + (size_t)(ncol + n) * ldb + k0 + kc,
                 (ncol + n) < N);
        }
    };

    load_tile(0, 0);
    CP_COMMIT();

    for (int kt = 0; kt < NT; kt++) {
        int st = kt & 1;
        if (kt + 1 < NT) load_tile(st ^ 1, kt + 1);
        CP_COMMIT();
        asm volatile("cp.async.wait_group 1;\n" ::: "memory");
        __syncthreads();

        const __half* As = AsB + st * H_ASTG;
        const __half* Bs = BsB + st * H_BSTG;
#pragma unroll
        for (int ks = 0; ks < 64; ks += 16) {
            uint32_t afr[2][4], bfr[8][2];
#pragma unroll
            for (int mt = 0; mt < 2; mt++) {
                ldsm_x4(afr[mt][0], afr[mt][1], afr[mt][2], afr[mt][3],
                        smem_u32(As + (warpM * 32 + mt * 16 + lr16) * 72 + ks + lk8));
            }
#pragma unroll
            for (int ntp = 0; ntp < 4; ntp++) {
                uint32_t q0, q1, q2, q3;
                ldsm_x4(q0, q1, q2, q3,
                        smem_u32(Bs + (warpN * 64 + ntp * 16 + lr16) * 72 + ks + lk8));
                bfr[2 * ntp][0]     = q0;
                bfr[2 * ntp + 1][0] = q1;
                bfr[2 * ntp][1]     = q2;
                bfr[2 * ntp + 1][1] = q3;
            }
#pragma unroll
            for (int mt = 0; mt < 2; mt++)
#pragma unroll
                for (int nt = 0; nt < 8; nt++)
                    mma_f16(acc[mt][nt], afr[mt], bfr[nt]);
        }
        __syncthreads();
    }

#pragma unroll
    for (int mt = 0; mt < 2; mt++) {
#pragma unroll
        for (int nt = 0; nt < 8; nt++) {
            int m0 = mrow + warpM * 32 + mt * 16 + g;
            int n0 = ncol + warpN * 64 + nt * 8 + 2 * t;
            if (n0 < N) {
                float b0 = bias[n0], b1 = bias[n0 + 1];
                if (m0 < M) {
                    __half2 h01 = __floats2half2_rn(acc[mt][nt][0] + b0,
                                                    acc[mt][nt][1] + b1);
                    *(uint32_t*)&C[(size_t)m0 * ldc + n0] = *(uint32_t*)&h01;
                }
                if (m0 + 8 < M) {
                    __half2 h23 = __floats2half2_rn(acc[mt][nt][2] + b0,
                                                    acc[mt][nt][3] + b1);
                    *(uint32_t*)&C[(size_t)(m0 + 8) * ldc + n0] = *(uint32_t*)&h23;
                }
            }
        }
    }
}

// -------------------- fused gates GEMM: BK=64, 2-stage ------------------------
// by < 31:  g2[by*64 .. +64) = E @ wih2^T          (K=320, NT=5)
// by == 31: g1[0..64)        = Xp @ wih1^T + bias2 (K=256, NT=4)
constexpr int H64_ASTG = 64 * 72;
constexpr int H64_BSTG = 128 * 72;
constexpr int SMEM_HG64 = ST2 * (H64_ASTG + H64_BSTG) * 2;   // 55296 B
__global__ void __launch_bounds__(256) k_gates(
    const __half* __restrict__ E, const __half* __restrict__ wih2,
    const __half* __restrict__ xph, const __half* __restrict__ wih1,
    const float* __restrict__ bias2,
    float* __restrict__ g2, float* __restrict__ g1)
{
    extern __shared__ __half sm[];
    __half* AsB = sm;
    __half* BsB = sm + ST2 * H64_ASTG;

    const int tid = threadIdx.x;
    const int lane = tid & 31;
    const int warpId = tid >> 5;
    const int warpM = warpId & 1;
    const int warpN = warpId >> 1;
    const int g = lane >> 2;
    const int t = lane & 3;
    const int lr16 = lane & 15;
    const int lk8 = (lane >> 4) * 8;

    const int ncol = blockIdx.x * 128;
    const bool isG1 = (blockIdx.y == 31);
    const __half* A  = isG1 ? xph : E + (size_t)blockIdx.y * 64 * KE;
    const __half* B  = isG1 ? wih1 : wih2;
    const int lda    = isG1 ? HH : KE;
    const int K      = isG1 ? HH : KE;
    float* C         = isG1 ? g1 : g2 + (size_t)blockIdx.y * 64 * GG;

    float acc[2][4][4];
#pragma unroll
    for (int mt = 0; mt < 2; mt++)
#pragma unroll
        for (int nt = 0; nt < 4; nt++)
#pragma unroll
            for (int q = 0; q < 4; q++) acc[mt][nt][q] = 0.f;

    const int NT = K >> 6;

    auto load_tile = [&](int st, int kt) {
        int k0 = kt << 6;
        __half* As = AsB + st * H64_ASTG;
        __half* Bs = BsB + st * H64_BSTG;
#pragma unroll
        for (int i = 0; i < 2; i++) {
            int c = tid + i * 256;
            int m = c >> 3, kc = (c & 7) * 8;
            cp16(As + m * 72 + kc, A + (size_t)m * lda + k0 + kc, true);
        }
#pragma unroll
        for (int i = 0; i < 4; i++) {
            int c = tid + i * 256;
            int n = c >> 3, kc = (c & 7) * 8;
            cp16(Bs + n * 72 + kc, B + (size_t)(ncol + n) * lda + k0 + kc, true);
        }
    };

    load_tile(0, 0);
    CP_COMMIT();

    for (int kt = 0; kt < NT; kt++) {
        int st = kt & 1;
        if (kt + 1 < NT) load_tile(st ^ 1, kt + 1);
        CP_COMMIT();
        asm volatile("cp.async.wait_group 1;\n" ::: "memory");
        __syncthreads();

        const __half* As = AsB + st * H64_ASTG;
        const __half* Bs = BsB + st * H64_BSTG;
#pragma unroll
        for (int ks = 0; ks < 64; ks += 16) {
            uint32_t afr[2][4], bfr[4][2];
#pragma unroll
            for (int mt = 0; mt < 2; mt++) {
                ldsm_x4(afr[mt][0], afr[mt][1], afr[mt][2], afr[mt][3],
                        smem_u32(As + (warpM * 32 + mt * 16 + lr16) * 72 + ks + lk8));
            }
#pragma unroll
            for (int ntp = 0; ntp < 2; ntp++) {
                uint32_t q0, q1, q2, q3;
                ldsm_x4(q0, q1, q2, q3,
                        smem_u32(Bs + (warpN * 32 + ntp * 16 + lr16) * 72 + ks + lk8));
                bfr[2 * ntp][0]     = q0;
                bfr[2 * ntp + 1][0] = q1;
                bfr[2 * ntp][1]     = q2;
                bfr[2 * ntp + 1][1] = q3;
            }
#pragma unroll
            for (int mt = 0; mt < 2; mt++)
#pragma unroll
                for (int nt = 0; nt < 4; nt++)
                    mma_f16(acc[mt][nt], afr[mt], bfr[nt]);
        }
        __syncthreads();
    }

#pragma unroll
    for (int mt = 0; mt < 2; mt++) {
#pragma unroll
        for (int nt = 0; nt < 4; nt++) {
            int m0 = warpM * 32 + mt * 16 + g;
            int n0 = ncol + warpN * 32 + nt * 8 + 2 * t;
            float b0 = 0.f, b1 = 0.f;
            if (isG1) { b0 = bias2[n0]; b1 = bias2[n0 + 1]; }
            C[(size_t)m0 * GG + n0]           = acc[mt][nt][0] + b0;
            C[(size_t)m0 * GG + n0 + 1]       = acc[mt][nt][1] + b1;
            C[(size_t)(m0 + 8) * GG + n0]     = acc[mt][nt][2] + b0;
            C[(size_t)(m0 + 8) * GG + n0 + 1] = acc[mt][nt][3] + b1;
        }
    }
}

// -------------------- recurrence: 4 clusters x 8 CTAs ------------------------
__global__ void __launch_bounds__(256, 1) __cluster_dims__(8, 1, 1)
k_rec(const float* __restrict__ w_hh) {
    __shared__ __align__(16) __half hs[16][264];
    __shared__ float gbuf[16][132];

    const int tid = threadIdx.x;
    const int lane = tid & 31;
    const int wid = tid >> 5;
    const int g = lane >> 2;
    const int t = lane & 3;
    const int lr16 = lane & 15;
    const int lk8 = (lane >> 4) * 8;
    const int rank = blockIdx.x & 7;
    const int grp = blockIdx.x >> 3;
    const int j0 = rank * 32;
    const int brow0 = grp * 16;

    uint32_t wb[2][16][2];
#pragma unroll
    for (int nt = 0; nt < 2; nt++) {
        int lc = wid * 16 + nt * 8 + g;
        int wrow = (lc >> 5) * 256 + j0 + (lc & 31);
        const float* wr = w_hh + (size_t)wrow * HH;
#pragma unroll
        for (int kt = 0; kt < 16; kt++) {
            __half2 h0 = __floats2half2_rn(wr[kt * 16 + 2 * t], wr[kt * 16 + 2 * t + 1]);
            __half2 h1 = __floats2half2_rn(wr[kt * 16 + 2 * t + 8], wr[kt * 16 + 2 * t + 9]);
            wb[nt][kt][0] = *(uint32_t*)&h0;
            wb[nt][kt][1] = *(uint32_t*)&h1;
        }
    }

    float creg[2] = {0.f, 0.f};
    const int crow = tid >> 4;
    const int cj2 = (tid & 15) * 2;
    int lc0[2], r0[2];
#pragma unroll
    for (int nt = 0; nt < 2; nt++) {
        lc0[nt] = wid * 16 + nt * 8 + 2 * t;
        r0[nt] = (lc0[nt] >> 5) * 256 + j0 + (lc0[nt] & 31);
    }

    // preload step-invariant G1 values (8 floats)
    float2 p0[2], p1[2];
#pragma unroll
    for (int nt = 0; nt < 2; nt++) {
        p0[nt] = *(const float2*)&d_g1[(size_t)(brow0 + g) * GG + r0[nt]];
        p1[nt] = *(const float2*)&d_g1[(size_t)(brow0 + g + 8) * GG + r0[nt]];
    }

    for (int s = 0; s < SS; s++) {
        const float* gp = d_g2 + ((size_t)s * BB + brow0) * GG;
        float2 q0[2], q1[2];
#pragma unroll
        for (int nt = 0; nt < 2; nt++) {
            q0[nt] = *(const float2*)&gp[(size_t)g * GG + r0[nt]];
            q1[nt] = *(const float2*)&gp[(size_t)(g + 8) * GG + r0[nt]];
        }

        float accA[2][4] = {{0.f, 0.f, 0.f, 0.f}, {0.f, 0.f, 0.f, 0.f}};
        float accB[2][4] = {{0.f, 0.f, 0.f, 0.f}, {0.f, 0.f, 0.f, 0.f}};

        if (s > 0) {
            const uint4* src = (const uint4*)(d_Hall + ((size_t)(s - 1) * BB + brow0) * HH);
#pragma unroll
            for (int i = 0; i < 2; i++) {
                int c = tid + i * 256;
                int m = c >> 5, kc = c & 31;
                *(uint4*)&hs[m][kc * 8] = src[m * 32 + kc];
            }
            __syncthreads();
#pragma unroll
            for (int kt = 0; kt < 16; kt++) {
                uint32_t af[4];
                ldsm_x4(af[0], af[1], af[2], af[3],
                        smem_u32(&hs[lr16][kt * 16 + lk8]));
                float* d0 = (kt < 8) ? accA[0] : accB[0];
                float* d1 = (kt < 8) ? accA[1] : accB[1];
                mma_f16(d0, af, wb[0][kt]);
                mma_f16(d1, af, wb[1][kt]);
            }
        }

#pragma unroll
        for (int nt = 0; nt < 2; nt++) {
            gbuf[g][lc0[nt]]         = accA[nt][0] + accB[nt][0] + q0[nt].x + p0[nt].x;
            gbuf[g][lc0[nt] + 1]     = accA[nt][1] + accB[nt][1] + q0[nt].y + p0[nt].y;
            gbuf[g + 8][lc0[nt]]     = accA[nt][2] + accB[nt][2] + q1[nt].x + p1[nt].x;
            gbuf[g + 8][lc0[nt] + 1] = accA[nt][3] + accB[nt][3] + q1[nt].y + p1[nt].y;
        }
        __syncthreads();

        {
            float hv[2];
#pragma unroll
            for (int e = 0; e < 2; e++) {
                int jj = cj2 + e;
                float gi = gbuf[crow][jj],      gf = gbuf[crow][32 + jj];
                float gc = gbuf[crow][64 + jj], go = gbuf[crow][96 + jj];
                float ii = fast_sigmoid(gi);
                float ff = fast_sigmoid(gf);
                float gv = fast_tanh(gc);
                float oo = fast_sigmoid(go);
                float cn = ff * creg[e] + ii * gv;
                creg[e] = cn;
                hv[e] = oo * fast_tanh(cn);
            }
            __half2 hp = __floats2half2_rn(hv[0], hv[1]);
            *(uint32_t*)&d_Hall[((size_t)s * BB + brow0 + crow) * HH + j0 + cj2] =
                *(uint32_t*)&hp;
        }

        if (s + 1 < SS) {
            asm volatile("barrier.cluster.arrive.aligned;" ::: "memory");
            asm volatile("barrier.cluster.wait.aligned;" ::: "memory");
        }
    }
}

// -------------------- fused one-hot + log-softmax (register-cached row) ------
constexpr int V8 = VV / 8;   // 1250 uint4 groups
__global__ void __launch_bounds__(256) k_softmax(float* __restrict__ out) {
    const int r = blockIdx.x;
    const int tid = threadIdx.x;
    if (r >= MROWS) {
        int b = r - MROWS;
        float* dst = out + (size_t)b * TT * VV;
        for (int v = tid * 4; v < VV; v += 1024) {
            float4 z = make_float4(0.f, 0.f, 0.f, 0.f);
            if (v == 0) z.y = 1.f;         // index 1 = START_ID
            __stcs((float4*)(dst + v), z);
        }
        return;
    }
    const int s = r >> 6, b = r & 63;
    const uint4* src = (const uint4*)(d_logits + (size_t)r * VV);

    uint4 vals[5];
    float m = -1e30f, sum = 0.f;
#pragma unroll
    for (int i = 0; i < 5; i++) {
        int c = tid + i * 256;
        if (c < V8) {
            uint4 u = src[c];
            vals[i] = u;
            float2 f0 = __half22float2(*(__half2*)&u.x);
            float2 f1 = __half22float2(*(__half2*)&u.y);
            float2 f2 = __half22float2(*(__half2*)&u.z);
            float2 f3 = __half22float2(*(__half2*)&u.w);
            float m8 = fmaxf(fmaxf(fmaxf(f0.x, f0.y), fmaxf(f1.x, f1.y)),
                             fmaxf(fmaxf(f2.x, f2.y), fmaxf(f3.x, f3.y)));
            if (m8 > m) { sum *= __expf(m - m8); m = m8; }
            sum += __expf(f0.x - m) + __expf(f0.y - m)
                 + __expf(f1.x - m) + __expf(f1.y - m)
                 + __expf(f2.x - m) + __expf(f2.y - m)
                 + __expf(f3.x - m) + __expf(f3.y - m);
        }
    }
#pragma unroll
    for (int o = 16; o; o >>= 1) {
        float mo = __shfl_xor_sync(0xffffffffu, m, o);
        float so = __shfl_xor_sync(0xffffffffu, sum, o);
        float M = fmaxf(m, mo);
        sum = sum * __expf(m - M) + so * __expf(mo - M);
        m = M;
    }
    __shared__ float sm_m[8], sm_s[8], s_lz;
    if ((tid & 31) == 0) { sm_m[tid >> 5] = m; sm_s[tid >> 5] = sum; }
    __syncthreads();
    if (tid == 0) {
        float M = sm_m[0], S = sm_s[0];
#pragma unroll
        for (int w = 1; w < 8; w++) {
            float mo = sm_m[w], so = sm_s[w];
            float MM = fmaxf(M, mo);
            S = S * __expf(M - MM) + so * __expf(mo - MM);
            M = MM;
        }
        s_lz = M + logf(S);
    }
    __syncthreads();
    const float lz = s_lz;
    float4* dst = (float4*)(out + ((size_t)b * TT + s + 1) * VV);
#pragma unroll
    for (int i = 0; i < 5; i++) {
        int c = tid + i * 256;
        if (c < V8) {
            uint4 u = vals[i];
            float2 f0 = __half22float2(*(__half2*)&u.x);
            float2 f1 = __half22float2(*(__half2*)&u.y);
            float2 f2 = __half22float2(*(__half2*)&u.z);
            float2 f3 = __half22float2(*(__half2*)&u.w);
            __stcs(&dst[2 * c],
                   make_float4(f0.x - lz, f0.y - lz, f1.x - lz, f1.y - lz));
            __stcs(&dst[2 * c + 1],
                   make_float4(f2.x - lz, f2.y - lz, f3.x - lz, f3.y - lz));
        }
    }
}

// -------------------- launch ------------------------------------------------
extern "C" void kernel_launch(void* const* d_in, const int* in_sizes, int n_in,
                              void* d_out, int out_size) {
    const float* X    = (const float*)d_in[0];
    const float* emb  = (const float*)d_in[1];
    const float* fc1w = (const float*)d_in[2];
    const float* fc1b = (const float*)d_in[3];
    const float* wih  = (const float*)d_in[4];
    const float* whh  = (const float*)d_in[5];
    const float* bih  = (const float*)d_in[6];
    const float* bhh  = (const float*)d_in[7];
    const float* fc2w = (const float*)d_in[8];
    const float* fc2b = (const float*)d_in[9];
    const int*   lab  = (const int*)d_in[10];
    float* out = (float*)d_out;

    __half *pXph, *pE, *pHall, *pW2h, *pWih1, *pWih2, *pLogits;
    float *pBias2, *pG1, *pG2;
    cudaGetSymbolAddress((void**)&pXph,    d_xph);
    cudaGetSymbolAddress((void**)&pE,      d_E);
    cudaGetSymbolAddress((void**)&pBias2,  d_bias2);
    cudaGetSymbolAddress((void**)&pG1,     d_g1);
    cudaGetSymbolAddress((void**)&pG2,     d_g2);
    cudaGetSymbolAddress((void**)&pHall,   d_Hall);
    cudaGetSymbolAddress((void**)&pLogits, d_logits);
    cudaGetSymbolAddress((void**)&pW2h,    d_w2h);
    cudaGetSymbolAddress((void**)&pWih1,   d_wih1h);
    cudaGetSymbolAddress((void**)&pWih2,   d_wih2h);

    static int attr_set = 0;
    if (!attr_set) {
        cudaFuncSetAttribute(k_hgemm,
                             cudaFuncAttributeMaxDynamicSharedMemorySize, SMEM_HG);
        cudaFuncSetAttribute(k_gates,
                             cudaFuncAttributeMaxDynamicSharedMemorySize, SMEM_HG64);
        attr_set = 1;
    }

    // front: fc1 split-K + bias2 + all elementwise converts, one wave
    k_front<<<NFRONT, 256>>>(X, fc1w, bih, bhh, emb, wih, fc2w, lab);
    k_fc1red<<<16, 256>>>(fc1b);

    // gates: G2 (248 CTAs, K=320) + G1 (8 CTAs, K=256), BK=64
    k_gates<<<dim3(8, 32), 256, SMEM_HG64>>>(pE, pWih2, pXph, pWih1, pBias2,
                                             pG2, pG1);

    // recurrence: 32 CTAs = 4 clusters x 8 (cluster barrier between steps)
    k_rec<<<32, 256>>>(whh);

    // fc2: logits[1984,10000] (fp16) = Hall @ w2h^T + fc2b, BK=64
    k_hgemm<<<dim3(79, 16), 256, SMEM_HG>>>(pHall, HH, pW2h, HH, fc2b,
                                            pLogits, VV, MROWS, VV, HH);

    k_softmax<<<MROWS + BB, 256>>>(out);
}